// round 6
// baseline (speedup 1.0000x reference)
#include <cuda_runtime.h>
#include <math.h>
#include <stdint.h>

#define NHEADS 16
#define HD 64
#define DM 1024
#define PDIM 64
#define MAXS 2048
#define MAXB 2
#define L2E 1.4426950408889634f

// scratch (device globals — no runtime allocation)
__device__ float g_masses[MAXB * NHEADS * MAXS];              // [B,H,S]
__device__ float g_invd[(size_t)MAXS * MAXS];                 // 1 / dist_sq_mod
__device__ float g_O[(size_t)MAXB * MAXS * DM];               // attention out (tf32 bits)
__device__ float g_Wc[(size_t)DM * DM];                       // W_out, tf32 bits

// ---------------- helpers ----------------
__device__ __forceinline__ uint32_t f2tf32(float f) {
    uint32_t u;
    asm("cvt.rna.tf32.f32 %0, %1;" : "=r"(u) : "f"(f));
    return u;
}
__device__ __forceinline__ float ex2(float x) {
    float y;
    asm("ex2.approx.ftz.f32 %0, %1;" : "=f"(y) : "f"(x));
    return y;
}
// D += A(16x8 tf32, row) * B(8x8 tf32, col), fp32 accum
__device__ __forceinline__ void mma_tf32(float* d, const uint32_t* a, const uint32_t* b) {
    asm volatile(
        "mma.sync.aligned.m16n8k8.row.col.f32.tf32.tf32.f32 "
        "{%0,%1,%2,%3}, {%4,%5,%6,%7}, {%8,%9}, {%0,%1,%2,%3};"
        : "+f"(d[0]), "+f"(d[1]), "+f"(d[2]), "+f"(d[3])
        : "r"(a[0]), "r"(a[1]), "r"(a[2]), "r"(a[3]), "r"(b[0]), "r"(b[1]));
}

// ---------------------------------------------------------------------------
// Kernel 1: masses[b,h,s] = softplus( dot(xh[b,s,h,:], W_mass[h,:]) )
// ---------------------------------------------------------------------------
__global__ void mass_kernel(const float* __restrict__ x,
                            const float* __restrict__ Wm, int S) {
    int gw   = (blockIdx.x * 256 + threadIdx.x) >> 5;
    int lane = threadIdx.x & 31;
    int s = gw % S;
    int h = (gw / S) & (NHEADS - 1);
    int b = gw / (S * NHEADS);
    const float* xr = x + ((size_t)(b * S + s)) * DM + h * HD;
    float t = xr[lane] * Wm[h * HD + lane] + xr[lane + 32] * Wm[h * HD + lane + 32];
#pragma unroll
    for (int o = 16; o; o >>= 1) t += __shfl_xor_sync(0xffffffffu, t, o);
    if (lane == 0) {
        float m = (t > 20.f) ? t : log1pf(expf(t));
        g_masses[(b * NHEADS + h) * S + s] = m;
    }
}

// ---------------------------------------------------------------------------
// Kernel 1b: pre-round W_out to tf32 bits
// ---------------------------------------------------------------------------
__global__ void wcvt_kernel(const float* __restrict__ W) {
    int i = blockIdx.x * 256 + threadIdx.x;
    float4 v = *(const float4*)&W[(size_t)i * 4];
    uint4 o;
    o.x = f2tf32(v.x); o.y = f2tf32(v.y); o.z = f2tf32(v.z); o.w = f2tf32(v.w);
    *(uint4*)&g_Wc[(size_t)i * 4] = o;
}

// ---------------------------------------------------------------------------
// Kernel 2: g_invd[i,j] = 1 / max( d2*(1+0.15*cos(sqrt(d2+1e-6))), 1e-6 )
// direct (a-b)^2 accumulation: diagonal exactly 0
// ---------------------------------------------------------------------------
__global__ void dist_kernel(const float* __restrict__ pos, int S) {
    __shared__ float Pi[PDIM][65];
    __shared__ float Pj[PDIM][65];
    int i0 = blockIdx.x * 64, j0 = blockIdx.y * 64;
    int tid = threadIdx.x;
#pragma unroll
    for (int v = 0; v < 16; v++) {
        int e = v * 256 + tid;
        int r = e >> 6, p = e & 63;
        Pi[p][r] = pos[(size_t)(i0 + r) * PDIM + p];
        Pj[p][r] = pos[(size_t)(j0 + r) * PDIM + p];
    }
    __syncthreads();
    int ty = tid >> 4, tx = tid & 15;
    float acc[4][4] = {};
#pragma unroll
    for (int p = 0; p < PDIM; p++) {
        float a[4], bb[4];
#pragma unroll
        for (int i = 0; i < 4; i++) a[i] = Pi[p][ty * 4 + i];
#pragma unroll
        for (int j = 0; j < 4; j++) bb[j] = Pj[p][tx * 4 + j];
#pragma unroll
        for (int i = 0; i < 4; i++)
#pragma unroll
            for (int j = 0; j < 4; j++) {
                float d = a[i] - bb[j];
                acc[i][j] = fmaf(d, d, acc[i][j]);
            }
    }
#pragma unroll
    for (int i = 0; i < 4; i++)
#pragma unroll
        for (int j = 0; j < 4; j++) {
            int ii = i0 + ty * 4 + i, jj = j0 + tx * 4 + j;
            float v = acc[i][j];
            float dn = sqrtf(v + 1e-6f);
            float d2 = v * (1.f + 0.15f * cosf(dn));
            d2 = fmaxf(d2, 1e-6f);
            g_invd[(size_t)ii * S + jj] = 1.0f / d2;
        }
}

// ---------------------------------------------------------------------------
// Kernel 3: attention, tf32 mma.sync, P generated DIRECTLY in A-fragment
// registers (never stored to SMEM). Block = (128-row i-tile, b*h),
// 8 warps x 16 rows. V double-buffered in pair-interleaved SMEM layout:
// group (ks,n) = 32B holding pairs (k=8ks+t, k=8ks+t+4) for t=0..3
// -> b-frag = one LDS.64, bank-conflict-free. One __syncthreads per j-tile.
// Rowsums: per-lane fp32 accumulators, folded by 2 quad shuffles at the end.
// ---------------------------------------------------------------------------
__global__ __launch_bounds__(256, 2)
void attn_kernel(const float* __restrict__ x,
                 const float* __restrict__ G, int S) {
    extern __shared__ char sm[];
    float* ms = (float*)sm;                       // [S] masses for this (b,h)
    char* vbuf = sm + (size_t)S * 4;              // 2 x 32KB V buffers

    int bh = blockIdx.y;
    int b = bh >> 4, h = bh & 15;
    int i0 = blockIdx.x * 128;
    int tid = threadIdx.x;
    int w = tid >> 5, lane = tid & 31;
    int g = lane >> 2, t = lane & 3;

    const float* mrow = &g_masses[(b * NHEADS + h) * S];
    for (int i = tid; i < S; i += 256) ms[i] = mrow[i];
    __syncthreads();

    float coefl = fabsf(G[h]) * L2E;
    float cm0 = coefl * ms[i0 + 16 * w + g];       // row r0 = i0+16w+g
    float cm1 = coefl * ms[i0 + 16 * w + g + 8];   // row r1 = r0+8
    const float CLAMP = 50.0f * L2E;

    float acc[8][4] = {};
    float rs0 = 0.f, rs1 = 0.f;

    const float* dr0 = &g_invd[(size_t)(i0 + 16 * w + g) * S];
    const float* dr1 = dr0 + (size_t)8 * S;

    int niter = S >> 7;
    for (int it = 0; it < niter; it++) {
        int jt = it << 7;
        char* vb = vbuf + (it & 1) * 32768;

        // ---- fill V buffer: thread owns 4 (ks,n) groups; 8 strided x loads
        // (coalesced across lanes), packed into 2x 16B stores.
#pragma unroll
        for (int v = 0; v < 4; v++) {
            int slot = v * 256 + tid;
            int ks = slot >> 6, n = slot & 63;
            const float* xp = &x[((size_t)(b * S + jt + 8 * ks)) * DM + h * HD + n];
            float e0 = xp[0],      e1 = xp[DM],     e2 = xp[2 * DM], e3 = xp[3 * DM];
            float e4 = xp[4 * DM], e5 = xp[5 * DM], e6 = xp[6 * DM], e7 = xp[7 * DM];
            uint4 p0, p1;
            p0.x = f2tf32(e0); p0.y = f2tf32(e4);   // pair t=0: (k0, k4)
            p0.z = f2tf32(e1); p0.w = f2tf32(e5);   // pair t=1
            p1.x = f2tf32(e2); p1.y = f2tf32(e6);   // pair t=2
            p1.z = f2tf32(e3); p1.w = f2tf32(e7);   // pair t=3
            char* dst = vb + (ks * 64 + n) * 32;
            *(uint4*)dst = p0;
            *(uint4*)(dst + 16) = p1;
        }
        __syncthreads();   // V[buf] ready; also proves mma(it-2) on this buf done

        // ---- generate P fragments in registers + MMA
        const float* d0 = dr0 + jt;
        const float* d1 = dr1 + jt;
#pragma unroll
        for (int ks = 0; ks < 16; ks++) {
            int c0 = 8 * ks + t, c1 = c0 + 4;
            float mj0 = ms[jt + c0], mj1 = ms[jt + c1];
            float f00 = fminf(cm0 * mj0 * d0[c0], CLAMP);
            float f01 = fminf(cm0 * mj1 * d0[c1], CLAMP);
            float f10 = fminf(cm1 * mj0 * d1[c0], CLAMP);
            float f11 = fminf(cm1 * mj1 * d1[c1], CLAMP);
            float e00 = ex2(f00), e01 = ex2(f01);
            float e10 = ex2(f10), e11 = ex2(f11);
            rs0 += e00 + e01;
            rs1 += e10 + e11;
            uint32_t a[4];
            a[0] = f2tf32(e00);   // A[g][t]
            a[1] = f2tf32(e10);   // A[g+8][t]
            a[2] = f2tf32(e01);   // A[g][t+4]
            a[3] = f2tf32(e11);   // A[g+8][t+4]
            const char* bk = vb + ks * 2048 + g * 32 + t * 8;
#pragma unroll
            for (int nt = 0; nt < 8; nt++) {
                uint2 bb = *(const uint2*)(bk + nt * 256);   // {B[8ks+t][n], B[8ks+t+4][n]}
                uint32_t br[2] = {bb.x, bb.y};
                mma_tf32(acc[nt], a, br);
            }
        }
        // no trailing sync: next fill targets the other buffer
    }

    // rowsum: fold the 4 lanes of each quad (t=0..3 partials)
    rs0 += __shfl_xor_sync(0xffffffffu, rs0, 1);
    rs0 += __shfl_xor_sync(0xffffffffu, rs0, 2);
    rs1 += __shfl_xor_sync(0xffffffffu, rs1, 1);
    rs1 += __shfl_xor_sync(0xffffffffu, rs1, 2);
    float r0 = 1.0f / rs0, r1 = 1.0f / rs1;

    size_t base0 = ((size_t)(b * S + i0 + 16 * w + g)) * DM + h * HD;
    size_t base1 = base0 + (size_t)8 * DM;
#pragma unroll
    for (int nt = 0; nt < 8; nt++) {
        int c = nt * 8 + 2 * t;
        float2 v0, v1;
        v0.x = __uint_as_float(f2tf32(acc[nt][0] * r0));
        v0.y = __uint_as_float(f2tf32(acc[nt][1] * r0));
        v1.x = __uint_as_float(f2tf32(acc[nt][2] * r1));
        v1.y = __uint_as_float(f2tf32(acc[nt][3] * r1));
        *(float2*)&g_O[base0 + c] = v0;
        *(float2*)&g_O[base1 + c] = v1;
    }
}

// ---------------------------------------------------------------------------
// Kernel 4: Y = O @ Wc^T, tf32 mma.sync, cp.async double-buffered.
// ---------------------------------------------------------------------------
__global__ __launch_bounds__(256, 2)
void out_gemm(float* __restrict__ Y) {
    extern __shared__ uint32_t sm_g[];
    uint32_t* As = sm_g;
    uint32_t* Bs = sm_g + 2 * 128 * 32;

    int n0 = blockIdx.y * 128, j0 = blockIdx.x * 128;
    int tid = threadIdx.x;
    int w = tid >> 5, lane = tid & 31;
    int g = lane >> 2, t = lane & 3;
    int wm = (w >> 2) * 64, wn = (w & 3) * 32;
    int swz = g << 2;

    float acc[4][4][4] = {};

    int cr[4], cc[4];
#pragma unroll
    for (int v = 0; v < 4; v++) {
        int idx4 = v * 256 + tid;
        cr[v] = idx4 >> 3;
        cc[v] = (idx4 & 7) * 4;
    }

#define OG_ISSUE(buf, k0)                                                        \
    do {                                                                         \
        _Pragma("unroll")                                                        \
        for (int v = 0; v < 4; v++) {                                            \
            int r = cr[v], c = cc[v];                                            \
            int so = r * 32 + (c ^ ((r & 7) << 2));                              \
            uint32_t dA = (uint32_t)__cvta_generic_to_shared(&As[(buf)*4096 + so]); \
            const float* sA = &g_O[(size_t)(n0 + r) * DM + (k0) + c];            \
            asm volatile("cp.async.cg.shared.global [%0], [%1], 16;" ::"r"(dA), "l"(sA)); \
            uint32_t dB = (uint32_t)__cvta_generic_to_shared(&Bs[(buf)*4096 + so]); \
            const float* sB = &g_Wc[(size_t)(j0 + r) * DM + (k0) + c];           \
            asm volatile("cp.async.cg.shared.global [%0], [%1], 16;" ::"r"(dB), "l"(sB)); \
        }                                                                        \
        asm volatile("cp.async.commit_group;");                                  \
    } while (0)

    OG_ISSUE(0, 0);

    for (int ki = 0; ki < DM / 32; ki++) {
        asm volatile("cp.async.wait_group 0;");
        __syncthreads();
        if (ki + 1 < DM / 32) OG_ISSUE((ki + 1) & 1, (ki + 1) * 32);

        const uint32_t* Ab = &As[(ki & 1) * 4096];
        const uint32_t* Bb = &Bs[(ki & 1) * 4096];
#pragma unroll
        for (int ks = 0; ks < 4; ks++) {
            int k = ks * 8;
            uint32_t a[4][4], bf[4][2];
#pragma unroll
            for (int mt = 0; mt < 4; mt++) {
                int r = wm + mt * 16 + g;
                a[mt][0] = Ab[r * 32 + ((k + t) ^ swz)];
                a[mt][1] = Ab[(r + 8) * 32 + ((k + t) ^ swz)];
                a[mt][2] = Ab[r * 32 + ((k + t + 4) ^ swz)];
                a[mt][3] = Ab[(r + 8) * 32 + ((k + t + 4) ^ swz)];
            }
#pragma unroll
            for (int nt = 0; nt < 4; nt++) {
                int r = wn + nt * 8 + g;
                bf[nt][0] = Bb[r * 32 + ((k + t) ^ swz)];
                bf[nt][1] = Bb[r * 32 + ((k + t + 4) ^ swz)];
            }
#pragma unroll
            for (int mt = 0; mt < 4; mt++)
#pragma unroll
                for (int nt = 0; nt < 4; nt++)
                    mma_tf32(acc[mt][nt], a[mt], bf[nt]);
        }
    }
#pragma unroll
    for (int mt = 0; mt < 4; mt++) {
        int m = n0 + wm + mt * 16 + g;
#pragma unroll
        for (int nt = 0; nt < 4; nt++) {
            int j = j0 + wn + nt * 8 + 2 * t;
            float2 v0, v1;
            v0.x = acc[mt][nt][0]; v0.y = acc[mt][nt][1];
            v1.x = acc[mt][nt][2]; v1.y = acc[mt][nt][3];
            *(float2*)&Y[(size_t)m * DM + j] = v0;
            *(float2*)&Y[(size_t)(m + 8) * DM + j] = v1;
        }
    }
}

// ---------------------------------------------------------------------------
extern "C" void kernel_launch(void* const* d_in, const int* in_sizes, int n_in,
                              void* d_out, int out_size) {
    const float* x   = (const float*)d_in[0];   // [B,S,1024]
    const float* pos = (const float*)d_in[1];   // [S,64]
    const float* Wm  = (const float*)d_in[2];   // [16,64]
    const float* G   = (const float*)d_in[3];   // [16]
    const float* Wo  = (const float*)d_in[4];   // [1024,1024]
    float* out = (float*)d_out;                 // [B,S,1024]

    int S = in_sizes[1] / PDIM;
    int B = in_sizes[0] / (S * DM);

    int ATTN_SMEM = S * 4 + 2 * 32768;          // masses + double-buffered V
    static const int GEMM_SMEM = 4 * 128 * 32 * 4;
    cudaFuncSetAttribute(attn_kernel, cudaFuncAttributeMaxDynamicSharedMemorySize, ATTN_SMEM);
    cudaFuncSetAttribute(out_gemm, cudaFuncAttributeMaxDynamicSharedMemorySize, GEMM_SMEM);

    int nwarps = B * NHEADS * S;
    mass_kernel<<<nwarps / 8, 256>>>(x, Wm, S);

    wcvt_kernel<<<DM * DM / 1024, 256>>>(Wo);

    dim3 gd(S / 64, S / 64);
    dist_kernel<<<gd, 256>>>(pos, S);

    dim3 ga(S / 128, B * NHEADS);
    attn_kernel<<<ga, 256, ATTN_SMEM>>>(x, G, S);

    dim3 gg(DM / 128, (B * S) / 128);
    out_gemm<<<gg, 256, GEMM_SMEM>>>(out);
}

// round 7
// speedup vs baseline: 1.0744x; 1.0744x over previous
#include <cuda_runtime.h>
#include <math.h>
#include <stdint.h>

#define NHEADS 16
#define HD 64
#define DM 1024
#define PDIM 64
#define MAXS 2048
#define MAXB 2
#define PSTRIDE 68            // P smem row stride (words); 68%32=4 -> frag reads conflict-free

// scratch (device globals — no runtime allocation)
__device__ float g_masses[MAXB * NHEADS * MAXS];              // [B,H,S]
__device__ float g_invd[(size_t)MAXS * MAXS];                 // 1 / dist_sq_mod
__device__ float g_O[(size_t)MAXB * MAXS * DM];               // attention out (tf32 bits)
__device__ float g_Wc[(size_t)DM * DM];                       // W_out, tf32 bits

// ---------------- helpers ----------------
__device__ __forceinline__ uint32_t f2tf32(float f) {
    uint32_t u;
    asm("cvt.rna.tf32.f32 %0, %1;" : "=r"(u) : "f"(f));
    return u;
}
__device__ __forceinline__ void mma_tf32(float* d, const uint32_t* a, const uint32_t* b) {
    asm volatile(
        "mma.sync.aligned.m16n8k8.row.col.f32.tf32.tf32.f32 "
        "{%0,%1,%2,%3}, {%4,%5,%6,%7}, {%8,%9}, {%0,%1,%2,%3};"
        : "+f"(d[0]), "+f"(d[1]), "+f"(d[2]), "+f"(d[3])
        : "r"(a[0]), "r"(a[1]), "r"(a[2]), "r"(a[3]), "r"(b[0]), "r"(b[1]));
}

// ---------------------------------------------------------------------------
// Kernel 1: masses[b,h,s] = softplus( dot(xh[b,s,h,:], W_mass[h,:]) )
// ---------------------------------------------------------------------------
__global__ void mass_kernel(const float* __restrict__ x,
                            const float* __restrict__ Wm, int S) {
    int gw   = (blockIdx.x * 256 + threadIdx.x) >> 5;
    int lane = threadIdx.x & 31;
    int s = gw % S;
    int h = (gw / S) & (NHEADS - 1);
    int b = gw / (S * NHEADS);
    const float* xr = x + ((size_t)(b * S + s)) * DM + h * HD;
    float t = xr[lane] * Wm[h * HD + lane] + xr[lane + 32] * Wm[h * HD + lane + 32];
#pragma unroll
    for (int o = 16; o; o >>= 1) t += __shfl_xor_sync(0xffffffffu, t, o);
    if (lane == 0) {
        float m = (t > 20.f) ? t : log1pf(expf(t));
        g_masses[(b * NHEADS + h) * S + s] = m;
    }
}

// ---------------------------------------------------------------------------
// Kernel 1b: pre-round W_out to tf32 bits
// ---------------------------------------------------------------------------
__global__ void wcvt_kernel(const float* __restrict__ W) {
    int i = blockIdx.x * 256 + threadIdx.x;
    float4 v = *(const float4*)&W[(size_t)i * 4];
    uint4 o;
    o.x = f2tf32(v.x); o.y = f2tf32(v.y); o.z = f2tf32(v.z); o.w = f2tf32(v.w);
    *(uint4*)&g_Wc[(size_t)i * 4] = o;
}

// ---------------------------------------------------------------------------
// Kernel 2: g_invd[i,j] = 1 / max( d2*(1+0.15*cos(sqrt(d2+1e-6))), 1e-6 )
// ---------------------------------------------------------------------------
__global__ void dist_kernel(const float* __restrict__ pos, int S) {
    __shared__ float Pi[PDIM][65];
    __shared__ float Pj[PDIM][65];
    int i0 = blockIdx.x * 64, j0 = blockIdx.y * 64;
    int tid = threadIdx.x;
#pragma unroll
    for (int v = 0; v < 16; v++) {
        int e = v * 256 + tid;
        int r = e >> 6, p = e & 63;
        Pi[p][r] = pos[(size_t)(i0 + r) * PDIM + p];
        Pj[p][r] = pos[(size_t)(j0 + r) * PDIM + p];
    }
    __syncthreads();
    int ty = tid >> 4, tx = tid & 15;
    float acc[4][4] = {};
#pragma unroll
    for (int p = 0; p < PDIM; p++) {
        float a[4], bb[4];
#pragma unroll
        for (int i = 0; i < 4; i++) a[i] = Pi[p][ty * 4 + i];
#pragma unroll
        for (int j = 0; j < 4; j++) bb[j] = Pj[p][tx * 4 + j];
#pragma unroll
        for (int i = 0; i < 4; i++)
#pragma unroll
            for (int j = 0; j < 4; j++) {
                float d = a[i] - bb[j];
                acc[i][j] = fmaf(d, d, acc[i][j]);
            }
    }
#pragma unroll
    for (int i = 0; i < 4; i++)
#pragma unroll
        for (int j = 0; j < 4; j++) {
            int ii = i0 + ty * 4 + i, jj = j0 + tx * 4 + j;
            float v = acc[i][j];
            float dn = sqrtf(v + 1e-6f);
            float d2 = v * (1.f + 0.15f * cosf(dn));
            d2 = fmaxf(d2, 1e-6f);
            g_invd[(size_t)ii * S + jj] = 1.0f / d2;
        }
}

// ---------------------------------------------------------------------------
// attn device pieces
// ---------------------------------------------------------------------------
// load next V subtile (64 k-rows x 64 n-cols) into 16 regs; coalesced
__device__ __forceinline__ void v_load(const float* __restrict__ x, int bS_jt,
                                       int h, int tid, float* vr) {
#pragma unroll
    for (int v = 0; v < 2; v++) {
        int slot = v * 256 + tid;
        int ks = slot >> 6, n = slot & 63;
        const float* xp = &x[((size_t)(bS_jt + 8 * ks)) * DM + h * HD + n];
#pragma unroll
        for (int j = 0; j < 8; j++) vr[v * 8 + j] = xp[(size_t)j * DM];
    }
}
// store V regs into pair-interleaved smem: group (ks,n) 32B = pairs (8ks+t, 8ks+t+4)
__device__ __forceinline__ void v_store(uint32_t* Vb, int tid, const float* vr) {
#pragma unroll
    for (int v = 0; v < 2; v++) {
        int slot = v * 256 + tid;
        int ks = slot >> 6, n = slot & 63;
        const float* e = vr + v * 8;
        uint4 p0, p1;
        p0.x = f2tf32(e[0]); p0.y = f2tf32(e[4]);
        p0.z = f2tf32(e[1]); p0.w = f2tf32(e[5]);
        p1.x = f2tf32(e[2]); p1.y = f2tf32(e[6]);
        p1.z = f2tf32(e[3]); p1.w = f2tf32(e[7]);
        uint32_t* dst = Vb + (ks * 64 + n) * 8;
        *(uint4*)dst = p0;
        *(uint4*)(dst + 4) = p1;
    }
}
// generate P subtile (128 x 64) + accumulate rowsums (halfwarp shuffle reduce)
__device__ __forceinline__ void p_gen(uint32_t* Pb, const float* ms, float* rowsum,
                                      int i0, int jt, int S, float coef,
                                      int w, int lane) {
    int hw = lane >> 4;             // 0/1: which row of the pair
    int c = 4 * (lane & 15);        // col within 64
#pragma unroll
    for (int v = 0; v < 8; v++) {
        int r = v * 16 + 2 * w + hw;
        float cm = coef * ms[i0 + r];
        float4 dv = *(const float4*)&g_invd[(size_t)(i0 + r) * S + jt + c];
        float4 mv = *(const float4*)&ms[jt + c];
        float e0 = __expf(fminf(cm * mv.x * dv.x, 50.f));
        float e1 = __expf(fminf(cm * mv.y * dv.y, 50.f));
        float e2 = __expf(fminf(cm * mv.z * dv.z, 50.f));
        float e3 = __expf(fminf(cm * mv.w * dv.w, 50.f));
        uint4 o;
        o.x = f2tf32(e0); o.y = f2tf32(e1); o.z = f2tf32(e2); o.w = f2tf32(e3);
        *(uint4*)&Pb[r * PSTRIDE + c] = o;
        float s = e0 + e1 + e2 + e3;
        s += __shfl_xor_sync(0xffffffffu, s, 1);
        s += __shfl_xor_sync(0xffffffffu, s, 2);
        s += __shfl_xor_sync(0xffffffffu, s, 4);
        s += __shfl_xor_sync(0xffffffffu, s, 8);
        if ((lane & 15) == 0) rowsum[r] += s;
    }
}

// ---------------------------------------------------------------------------
// Kernel 3: attention, tf32 mma.sync, double-buffered 128x64 P / 64x64 V
// subtiles, one __syncthreads per subtile. Warp tile 32x32 (4m x 2n grid).
// ---------------------------------------------------------------------------
__global__ __launch_bounds__(256, 2)
void attn_kernel(const float* __restrict__ x,
                 const float* __restrict__ G, int S) {
    extern __shared__ char sm[];
    float* ms = (float*)sm;                          // [S]
    float* rowsum = ms + S;                          // [128]
    uint32_t* Pbuf = (uint32_t*)(rowsum + 128);      // 2 x [128*PSTRIDE]
    uint32_t* Vbuf = Pbuf + 2 * 128 * PSTRIDE;       // 2 x [4096]

    int bh = blockIdx.y;
    int b = bh >> 4, h = bh & 15;
    int i0 = blockIdx.x * 128;
    int tid = threadIdx.x;
    int w = tid >> 5, lane = tid & 31;
    int g = lane >> 2, t = lane & 3;
    int wm = (w >> 1) * 32, wn = (w & 1) * 32;
    float coef = fabsf(G[h]);

    const float* mrow = &g_masses[(b * NHEADS + h) * S];
    for (int i = tid; i < S; i += 256) ms[i] = mrow[i];
    if (tid < 128) rowsum[tid] = 0.f;
    __syncthreads();

    float acc[2][4][4] = {};
    int nsub = S >> 6;
    int bS = b * S;

    // prologue: fill buffer 0 with subtile 0
    {
        float vr[16];
        v_load(x, bS + 0, h, tid, vr);
        v_store(Vbuf, tid, vr);
        p_gen(Pbuf, ms, rowsum, i0, 0, S, coef, w, lane);
    }
    __syncthreads();

    for (int s = 0; s < nsub; s++) {
        int buf = s & 1;
        uint32_t* Pb = Pbuf + buf * 128 * PSTRIDE;
        uint32_t* Vb = Vbuf + buf * 4096;
        int nxt = s + 1;
        bool has = nxt < nsub;

        float vr[16];
        if (has) v_load(x, bS + (nxt << 6), h, tid, vr);   // prefetch next V

        // MMA on current buffers
#pragma unroll
        for (int ks = 0; ks < 8; ks++) {
            int k = 8 * ks;
            uint32_t a[2][4];
#pragma unroll
            for (int mt = 0; mt < 2; mt++) {
                int r = wm + 16 * mt + g;
                a[mt][0] = Pb[r * PSTRIDE + k + t];
                a[mt][1] = Pb[(r + 8) * PSTRIDE + k + t];
                a[mt][2] = Pb[r * PSTRIDE + k + t + 4];
                a[mt][3] = Pb[(r + 8) * PSTRIDE + k + t + 4];
            }
#pragma unroll
            for (int nt = 0; nt < 4; nt++) {
                uint2 bb = *(const uint2*)(Vb + ks * 512 + (wn + nt * 8 + g) * 8 + t * 2);
                uint32_t br[2] = {bb.x, bb.y};
#pragma unroll
                for (int mt = 0; mt < 2; mt++) mma_tf32(acc[mt][nt], a[mt], br);
            }
        }

        if (has) {
            uint32_t* Pn = Pbuf + (buf ^ 1) * 128 * PSTRIDE;
            uint32_t* Vn = Vbuf + (buf ^ 1) * 4096;
            v_store(Vn, tid, vr);
            p_gen(Pn, ms, rowsum, i0, nxt << 6, S, coef, w, lane);
        }
        __syncthreads();
    }

    // epilogue: normalize + write tf32-rounded
#pragma unroll
    for (int mt = 0; mt < 2; mt++) {
        int r0 = wm + 16 * mt + g;
        float rv0 = 1.0f / rowsum[r0];
        float rv1 = 1.0f / rowsum[r0 + 8];
        size_t base0 = ((size_t)(bS + i0 + r0)) * DM + h * HD;
        size_t base1 = base0 + (size_t)8 * DM;
#pragma unroll
        for (int nt = 0; nt < 4; nt++) {
            int c = wn + nt * 8 + 2 * t;
            float2 v0, v1;
            v0.x = __uint_as_float(f2tf32(acc[mt][nt][0] * rv0));
            v0.y = __uint_as_float(f2tf32(acc[mt][nt][1] * rv0));
            v1.x = __uint_as_float(f2tf32(acc[mt][nt][2] * rv1));
            v1.y = __uint_as_float(f2tf32(acc[mt][nt][3] * rv1));
            *(float2*)&g_O[base0 + c] = v0;
            *(float2*)&g_O[base1 + c] = v1;
        }
    }
}

// ---------------------------------------------------------------------------
// Kernel 4: Y = O @ Wc^T, tf32 mma.sync, cp.async double-buffered.
// ---------------------------------------------------------------------------
__global__ __launch_bounds__(256, 2)
void out_gemm(float* __restrict__ Y) {
    extern __shared__ uint32_t sm_g[];
    uint32_t* As = sm_g;
    uint32_t* Bs = sm_g + 2 * 128 * 32;

    int n0 = blockIdx.y * 128, j0 = blockIdx.x * 128;
    int tid = threadIdx.x;
    int w = tid >> 5, lane = tid & 31;
    int g = lane >> 2, t = lane & 3;
    int wm = (w >> 2) * 64, wn = (w & 3) * 32;
    int swz = g << 2;

    float acc[4][4][4] = {};

    int cr[4], cc[4];
#pragma unroll
    for (int v = 0; v < 4; v++) {
        int idx4 = v * 256 + tid;
        cr[v] = idx4 >> 3;
        cc[v] = (idx4 & 7) * 4;
    }

#define OG_ISSUE(buf, k0)                                                        \
    do {                                                                         \
        _Pragma("unroll")                                                        \
        for (int v = 0; v < 4; v++) {                                            \
            int r = cr[v], c = cc[v];                                            \
            int so = r * 32 + (c ^ ((r & 7) << 2));                              \
            uint32_t dA = (uint32_t)__cvta_generic_to_shared(&As[(buf)*4096 + so]); \
            const float* sA = &g_O[(size_t)(n0 + r) * DM + (k0) + c];            \
            asm volatile("cp.async.cg.shared.global [%0], [%1], 16;" ::"r"(dA), "l"(sA)); \
            uint32_t dB = (uint32_t)__cvta_generic_to_shared(&Bs[(buf)*4096 + so]); \
            const float* sB = &g_Wc[(size_t)(j0 + r) * DM + (k0) + c];           \
            asm volatile("cp.async.cg.shared.global [%0], [%1], 16;" ::"r"(dB), "l"(sB)); \
        }                                                                        \
        asm volatile("cp.async.commit_group;");                                  \
    } while (0)

    OG_ISSUE(0, 0);

    for (int ki = 0; ki < DM / 32; ki++) {
        asm volatile("cp.async.wait_group 0;");
        __syncthreads();
        if (ki + 1 < DM / 32) OG_ISSUE((ki + 1) & 1, (ki + 1) * 32);

        const uint32_t* Ab = &As[(ki & 1) * 4096];
        const uint32_t* Bb = &Bs[(ki & 1) * 4096];
#pragma unroll
        for (int ks = 0; ks < 4; ks++) {
            int k = ks * 8;
            uint32_t a[4][4], bf[4][2];
#pragma unroll
            for (int mt = 0; mt < 4; mt++) {
                int r = wm + mt * 16 + g;
                a[mt][0] = Ab[r * 32 + ((k + t) ^ swz)];
                a[mt][1] = Ab[(r + 8) * 32 + ((k + t) ^ swz)];
                a[mt][2] = Ab[r * 32 + ((k + t + 4) ^ swz)];
                a[mt][3] = Ab[(r + 8) * 32 + ((k + t + 4) ^ swz)];
            }
#pragma unroll
            for (int nt = 0; nt < 4; nt++) {
                int r = wn + nt * 8 + g;
                bf[nt][0] = Bb[r * 32 + ((k + t) ^ swz)];
                bf[nt][1] = Bb[r * 32 + ((k + t + 4) ^ swz)];
            }
#pragma unroll
            for (int mt = 0; mt < 4; mt++)
#pragma unroll
                for (int nt = 0; nt < 4; nt++)
                    mma_tf32(acc[mt][nt], a[mt], bf[nt]);
        }
    }
#pragma unroll
    for (int mt = 0; mt < 4; mt++) {
        int m = n0 + wm + mt * 16 + g;
#pragma unroll
        for (int nt = 0; nt < 4; nt++) {
            int j = j0 + wn + nt * 8 + 2 * t;
            float2 v0, v1;
            v0.x = acc[mt][nt][0]; v0.y = acc[mt][nt][1];
            v1.x = acc[mt][nt][2]; v1.y = acc[mt][nt][3];
            *(float2*)&Y[(size_t)m * DM + j] = v0;
            *(float2*)&Y[(size_t)(m + 8) * DM + j] = v1;
        }
    }
}

// ---------------------------------------------------------------------------
extern "C" void kernel_launch(void* const* d_in, const int* in_sizes, int n_in,
                              void* d_out, int out_size) {
    const float* x   = (const float*)d_in[0];   // [B,S,1024]
    const float* pos = (const float*)d_in[1];   // [S,64]
    const float* Wm  = (const float*)d_in[2];   // [16,64]
    const float* G   = (const float*)d_in[3];   // [16]
    const float* Wo  = (const float*)d_in[4];   // [1024,1024]
    float* out = (float*)d_out;                 // [B,S,1024]

    int S = in_sizes[1] / PDIM;
    int B = in_sizes[0] / (S * DM);

    int ATTN_SMEM = S * 4 + 512 + 2 * 128 * PSTRIDE * 4 + 2 * 4096 * 4;
    static const int GEMM_SMEM = 4 * 128 * 32 * 4;
    cudaFuncSetAttribute(attn_kernel, cudaFuncAttributeMaxDynamicSharedMemorySize, ATTN_SMEM);
    cudaFuncSetAttribute(out_gemm, cudaFuncAttributeMaxDynamicSharedMemorySize, GEMM_SMEM);

    int nwarps = B * NHEADS * S;
    mass_kernel<<<nwarps / 8, 256>>>(x, Wm, S);

    wcvt_kernel<<<DM * DM / 1024, 256>>>(Wo);

    dim3 gd(S / 64, S / 64);
    dist_kernel<<<gd, 256>>>(pos, S);

    dim3 ga(S / 128, B * NHEADS);
    attn_kernel<<<ga, 256, ATTN_SMEM>>>(x, G, S);

    dim3 gg(DM / 128, (B * S) / 128);
    out_gemm<<<gg, 256, GEMM_SMEM>>>(out);
}

// round 8
// speedup vs baseline: 1.5805x; 1.4710x over previous
#include <cuda_runtime.h>
#include <cuda_fp16.h>
#include <math.h>
#include <stdint.h>

#define NHEADS 16
#define HD 64
#define DM 1024
#define PDIM 64
#define MAXS 2048
#define MAXB 2
#define L2E 1.4426950408889634f
#define PSTR 68     // P smem row stride in words (fp16x2); a-frag banks 4g+t distinct
#define VSTR 72     // V smem row stride in words (fp16x2); b-frag banks 8t+g distinct

// scratch (device globals — no runtime allocation)
__device__ float g_masses[MAXB * NHEADS * MAXS];              // [B,H,S]
__device__ float g_invd[(size_t)MAXS * MAXS];                 // 1 / dist_sq_mod
__device__ float g_O[(size_t)MAXB * MAXS * DM];               // attention out (tf32 bits)
__device__ float g_Wc[(size_t)DM * DM];                       // W_out, tf32 bits

// ---------------- helpers ----------------
__device__ __forceinline__ uint32_t f2tf32(float f) {
    uint32_t u;
    asm("cvt.rna.tf32.f32 %0, %1;" : "=r"(u) : "f"(f));
    return u;
}
__device__ __forceinline__ float ex2(float v) {
    float y;
    asm("ex2.approx.ftz.f32 %0, %1;" : "=f"(y) : "f"(v));
    return y;
}
// tf32 m16n8k8 (out_gemm)
__device__ __forceinline__ void mma_tf32(float* d, const uint32_t* a, const uint32_t* b) {
    asm volatile(
        "mma.sync.aligned.m16n8k8.row.col.f32.tf32.tf32.f32 "
        "{%0,%1,%2,%3}, {%4,%5,%6,%7}, {%8,%9}, {%0,%1,%2,%3};"
        : "+f"(d[0]), "+f"(d[1]), "+f"(d[2]), "+f"(d[3])
        : "r"(a[0]), "r"(a[1]), "r"(a[2]), "r"(a[3]), "r"(b[0]), "r"(b[1]));
}
// fp16 m16n8k16, fp32 accum (attention)
__device__ __forceinline__ void mma_f16(float* d, const uint32_t* a, const uint32_t* b) {
    asm volatile(
        "mma.sync.aligned.m16n8k16.row.col.f32.f16.f16.f32 "
        "{%0,%1,%2,%3}, {%4,%5,%6,%7}, {%8,%9}, {%0,%1,%2,%3};"
        : "+f"(d[0]), "+f"(d[1]), "+f"(d[2]), "+f"(d[3])
        : "r"(a[0]), "r"(a[1]), "r"(a[2]), "r"(a[3]), "r"(b[0]), "r"(b[1]));
}

// ---------------------------------------------------------------------------
// Kernel 1: masses[b,h,s] = softplus( dot(xh[b,s,h,:], W_mass[h,:]) )
// ---------------------------------------------------------------------------
__global__ void mass_kernel(const float* __restrict__ x,
                            const float* __restrict__ Wm, int S) {
    int gw   = (blockIdx.x * 256 + threadIdx.x) >> 5;
    int lane = threadIdx.x & 31;
    int s = gw % S;
    int h = (gw / S) & (NHEADS - 1);
    int b = gw / (S * NHEADS);
    const float* xr = x + ((size_t)(b * S + s)) * DM + h * HD;
    float t = xr[lane] * Wm[h * HD + lane] + xr[lane + 32] * Wm[h * HD + lane + 32];
#pragma unroll
    for (int o = 16; o; o >>= 1) t += __shfl_xor_sync(0xffffffffu, t, o);
    if (lane == 0) {
        float m = (t > 20.f) ? t : log1pf(expf(t));
        g_masses[(b * NHEADS + h) * S + s] = m;
    }
}

// ---------------------------------------------------------------------------
// Kernel 1b: pre-round W_out to tf32 bits
// ---------------------------------------------------------------------------
__global__ void wcvt_kernel(const float* __restrict__ W) {
    int i = blockIdx.x * 256 + threadIdx.x;
    float4 v = *(const float4*)&W[(size_t)i * 4];
    uint4 o;
    o.x = f2tf32(v.x); o.y = f2tf32(v.y); o.z = f2tf32(v.z); o.w = f2tf32(v.w);
    *(uint4*)&g_Wc[(size_t)i * 4] = o;
}

// ---------------------------------------------------------------------------
// Kernel 2: g_invd[i,j] = 1 / max( d2*(1+0.15*cos(sqrt(d2+1e-6))), 1e-6 )
// direct (a-b)^2 accumulation: diagonal exactly 0
// ---------------------------------------------------------------------------
__global__ void dist_kernel(const float* __restrict__ pos, int S) {
    __shared__ float Pi[PDIM][65];
    __shared__ float Pj[PDIM][65];
    int i0 = blockIdx.x * 64, j0 = blockIdx.y * 64;
    int tid = threadIdx.x;
#pragma unroll
    for (int v = 0; v < 16; v++) {
        int e = v * 256 + tid;
        int r = e >> 6, p = e & 63;
        Pi[p][r] = pos[(size_t)(i0 + r) * PDIM + p];
        Pj[p][r] = pos[(size_t)(j0 + r) * PDIM + p];
    }
    __syncthreads();
    int ty = tid >> 4, tx = tid & 15;
    float acc[4][4] = {};
#pragma unroll
    for (int p = 0; p < PDIM; p++) {
        float a[4], bb[4];
#pragma unroll
        for (int i = 0; i < 4; i++) a[i] = Pi[p][ty * 4 + i];
#pragma unroll
        for (int j = 0; j < 4; j++) bb[j] = Pj[p][tx * 4 + j];
#pragma unroll
        for (int i = 0; i < 4; i++)
#pragma unroll
            for (int j = 0; j < 4; j++) {
                float d = a[i] - bb[j];
                acc[i][j] = fmaf(d, d, acc[i][j]);
            }
    }
#pragma unroll
    for (int i = 0; i < 4; i++)
#pragma unroll
        for (int j = 0; j < 4; j++) {
            int ii = i0 + ty * 4 + i, jj = j0 + tx * 4 + j;
            float v = acc[i][j];
            float dn = sqrtf(v + 1e-6f);
            float d2 = v * (1.f + 0.15f * cosf(dn));
            d2 = fmaxf(d2, 1e-6f);
            g_invd[(size_t)ii * S + jj] = 1.0f / d2;
        }
}

// ---------------------------------------------------------------------------
// Kernel 3: attention in fp16 (P' = exp(f-50), range (0,1]); R4 phase
// structure: [fill V + gen P] / sync / [MMA] / sync. Warp = 16 rows x 64 cols.
// Rowsum via ones-MMA on the ROUNDED fp16 P (consistent normalization);
// the e^-50 scale cancels in softmax.
// ---------------------------------------------------------------------------
__global__ __launch_bounds__(256, 2)
void attn_kernel(const float* __restrict__ x,
                 const float* __restrict__ G, int S) {
    extern __shared__ char sm[];
    float* ms = (float*)sm;                        // [S] masses for this (b,h)
    uint32_t* Ph = (uint32_t*)(sm + (size_t)S * 4);  // [128][PSTR] fp16x2 pairs (j)
    uint32_t* Vb = Ph + 128 * PSTR;                // [64][VSTR] fp16x2 pairs (k)

    int bh = blockIdx.y;
    int b = bh >> 4, h = bh & 15;
    int i0 = blockIdx.x * 128;
    int tid = threadIdx.x;
    int w = tid >> 5, lane = tid & 31;
    int g = lane >> 2, t = lane & 3;
    int wm = 16 * w;
    int bS = b * S;

    const float* mrow = &g_masses[(b * NHEADS + h) * S];
    for (int i = tid; i < S; i += 256) ms[i] = mrow[i];
    __syncthreads();

    float coefl = fabsf(G[h]) * L2E;
    const float C50L = 50.0f * L2E;

    float acc[8][4] = {};
    float sacc[4] = {};
    int niter = S >> 7;

    for (int it = 0; it < niter; it++) {
        int jt = it << 7;

        // ---- V fill: Vb[k2][n] = {V[2k2][n], V[2k2+1][n]} fp16x2
#pragma unroll
        for (int v4 = 0; v4 < 4; v4++) {
            int slot = v4 * 256 + tid;
            int n4 = slot & 15, k2 = slot >> 4;
            const float* xp = &x[((size_t)(bS + jt + 2 * k2)) * DM + h * HD + n4 * 4];
            float4 r0 = *(const float4*)xp;
            float4 r1 = *(const float4*)(xp + DM);
            __half2 h0 = __floats2half2_rn(r0.x, r1.x);
            __half2 h1 = __floats2half2_rn(r0.y, r1.y);
            __half2 h2 = __floats2half2_rn(r0.z, r1.z);
            __half2 h3 = __floats2half2_rn(r0.w, r1.w);
            uint4 o;
            o.x = *(uint32_t*)&h0; o.y = *(uint32_t*)&h1;
            o.z = *(uint32_t*)&h2; o.w = *(uint32_t*)&h3;
            *(uint4*)&Vb[k2 * VSTR + n4 * 4] = o;
        }
        // ---- P gen: row per (v,w); 4 cols/thread; P' = exp2(min(fL,C)-C)
#pragma unroll
        for (int v = 0; v < 16; v++) {
            int r = v * 8 + w;
            float cm = coefl * ms[i0 + r];
            float4 dv = *(const float4*)&g_invd[(size_t)(i0 + r) * S + jt + 4 * lane];
            float4 mv = *(const float4*)&ms[jt + 4 * lane];
            float e0 = ex2(fminf(cm * mv.x * dv.x, C50L) - C50L);
            float e1 = ex2(fminf(cm * mv.y * dv.y, C50L) - C50L);
            float e2 = ex2(fminf(cm * mv.z * dv.z, C50L) - C50L);
            float e3 = ex2(fminf(cm * mv.w * dv.w, C50L) - C50L);
            __half2 p0 = __floats2half2_rn(e0, e1);
            __half2 p1 = __floats2half2_rn(e2, e3);
            uint2 o;
            o.x = *(uint32_t*)&p0; o.y = *(uint32_t*)&p1;
            *(uint2*)&Ph[r * PSTR + 2 * lane] = o;
        }
        __syncthreads();   // tiles ready

        // ---- MMA: 8 k16-chunks x (8 n-tiles + rowsum)
#pragma unroll
        for (int kc = 0; kc < 8; kc++) {
            uint32_t a[4];
            int ra = (wm + g) * PSTR + 8 * kc + t;
            int rb = ra + 8 * PSTR;
            a[0] = Ph[ra];     a[1] = Ph[rb];
            a[2] = Ph[ra + 4]; a[3] = Ph[rb + 4];
#pragma unroll
            for (int nt = 0; nt < 8; nt++) {
                uint32_t br[2];
                br[0] = Vb[(8 * kc + t) * VSTR + nt * 8 + g];
                br[1] = Vb[(8 * kc + t + 4) * VSTR + nt * 8 + g];
                mma_f16(acc[nt], a, br);
            }
            uint32_t ones[2] = {0x3C003C00u, 0x3C003C00u};
            mma_f16(sacc, a, ones);
        }
        __syncthreads();   // MMA reads done before next fill
    }

    float r0 = 1.0f / sacc[0];
    float r1 = 1.0f / sacc[2];
    size_t base0 = ((size_t)(bS + i0 + wm + g)) * DM + h * HD;
    size_t base1 = base0 + (size_t)8 * DM;
#pragma unroll
    for (int nt = 0; nt < 8; nt++) {
        int c = nt * 8 + 2 * t;
        float2 v0, v1;
        v0.x = __uint_as_float(f2tf32(acc[nt][0] * r0));
        v0.y = __uint_as_float(f2tf32(acc[nt][1] * r0));
        v1.x = __uint_as_float(f2tf32(acc[nt][2] * r1));
        v1.y = __uint_as_float(f2tf32(acc[nt][3] * r1));
        *(float2*)&g_O[base0 + c] = v0;
        *(float2*)&g_O[base1 + c] = v1;
    }
}

// ---------------------------------------------------------------------------
// Kernel 4: Y = O @ Wc^T, tf32 mma.sync, cp.async double-buffered.
// ---------------------------------------------------------------------------
__global__ __launch_bounds__(256, 2)
void out_gemm(float* __restrict__ Y) {
    extern __shared__ uint32_t sm_g[];
    uint32_t* As = sm_g;
    uint32_t* Bs = sm_g + 2 * 128 * 32;

    int n0 = blockIdx.y * 128, j0 = blockIdx.x * 128;
    int tid = threadIdx.x;
    int w = tid >> 5, lane = tid & 31;
    int g = lane >> 2, t = lane & 3;
    int wm = (w >> 2) * 64, wn = (w & 3) * 32;
    int swz = g << 2;

    float acc[4][4][4] = {};

    int cr[4], cc[4];
#pragma unroll
    for (int v = 0; v < 4; v++) {
        int idx4 = v * 256 + tid;
        cr[v] = idx4 >> 3;
        cc[v] = (idx4 & 7) * 4;
    }

#define OG_ISSUE(buf, k0)                                                        \
    do {                                                                         \
        _Pragma("unroll")                                                        \
        for (int v = 0; v < 4; v++) {                                            \
            int r = cr[v], c = cc[v];                                            \
            int so = r * 32 + (c ^ ((r & 7) << 2));                              \
            uint32_t dA = (uint32_t)__cvta_generic_to_shared(&As[(buf)*4096 + so]); \
            const float* sA = &g_O[(size_t)(n0 + r) * DM + (k0) + c];            \
            asm volatile("cp.async.cg.shared.global [%0], [%1], 16;" ::"r"(dA), "l"(sA)); \
            uint32_t dB = (uint32_t)__cvta_generic_to_shared(&Bs[(buf)*4096 + so]); \
            const float* sB = &g_Wc[(size_t)(j0 + r) * DM + (k0) + c];           \
            asm volatile("cp.async.cg.shared.global [%0], [%1], 16;" ::"r"(dB), "l"(sB)); \
        }                                                                        \
        asm volatile("cp.async.commit_group;");                                  \
    } while (0)

    OG_ISSUE(0, 0);

    for (int ki = 0; ki < DM / 32; ki++) {
        asm volatile("cp.async.wait_group 0;");
        __syncthreads();
        if (ki + 1 < DM / 32) OG_ISSUE((ki + 1) & 1, (ki + 1) * 32);

        const uint32_t* Ab = &As[(ki & 1) * 4096];
        const uint32_t* Bb = &Bs[(ki & 1) * 4096];
#pragma unroll
        for (int ks = 0; ks < 4; ks++) {
            int k = ks * 8;
            uint32_t a[4][4], bf[4][2];
#pragma unroll
            for (int mt = 0; mt < 4; mt++) {
                int r = wm + mt * 16 + g;
                a[mt][0] = Ab[r * 32 + ((k + t) ^ swz)];
                a[mt][1] = Ab[(r + 8) * 32 + ((k + t) ^ swz)];
                a[mt][2] = Ab[r * 32 + ((k + t + 4) ^ swz)];
                a[mt][3] = Ab[(r + 8) * 32 + ((k + t + 4) ^ swz)];
            }
#pragma unroll
            for (int nt = 0; nt < 4; nt++) {
                int r = wn + nt * 8 + g;
                bf[nt][0] = Bb[r * 32 + ((k + t) ^ swz)];
                bf[nt][1] = Bb[r * 32 + ((k + t + 4) ^ swz)];
            }
#pragma unroll
            for (int mt = 0; mt < 4; mt++)
#pragma unroll
                for (int nt = 0; nt < 4; nt++)
                    mma_tf32(acc[mt][nt], a[mt], bf[nt]);
        }
    }
#pragma unroll
    for (int mt = 0; mt < 4; mt++) {
        int m = n0 + wm + mt * 16 + g;
#pragma unroll
        for (int nt = 0; nt < 4; nt++) {
            int j = j0 + wn + nt * 8 + 2 * t;
            float2 v0, v1;
            v0.x = acc[mt][nt][0]; v0.y = acc[mt][nt][1];
            v1.x = acc[mt][nt][2]; v1.y = acc[mt][nt][3];
            *(float2*)&Y[(size_t)m * DM + j] = v0;
            *(float2*)&Y[(size_t)(m + 8) * DM + j] = v1;
        }
    }
}

// ---------------------------------------------------------------------------
extern "C" void kernel_launch(void* const* d_in, const int* in_sizes, int n_in,
                              void* d_out, int out_size) {
    const float* x   = (const float*)d_in[0];   // [B,S,1024]
    const float* pos = (const float*)d_in[1];   // [S,64]
    const float* Wm  = (const float*)d_in[2];   // [16,64]
    const float* G   = (const float*)d_in[3];   // [16]
    const float* Wo  = (const float*)d_in[4];   // [1024,1024]
    float* out = (float*)d_out;                 // [B,S,1024]

    int S = in_sizes[1] / PDIM;
    int B = in_sizes[0] / (S * DM);

    int ATTN_SMEM = S * 4 + 128 * PSTR * 4 + 64 * VSTR * 4;
    static const int GEMM_SMEM = 4 * 128 * 32 * 4;
    cudaFuncSetAttribute(attn_kernel, cudaFuncAttributeMaxDynamicSharedMemorySize, ATTN_SMEM);
    cudaFuncSetAttribute(out_gemm, cudaFuncAttributeMaxDynamicSharedMemorySize, GEMM_SMEM);

    int nwarps = B * NHEADS * S;
    mass_kernel<<<nwarps / 8, 256>>>(x, Wm, S);

    wcvt_kernel<<<DM * DM / 1024, 256>>>(Wo);

    dim3 gd(S / 64, S / 64);
    dist_kernel<<<gd, 256>>>(pos, S);

    dim3 ga(S / 128, B * NHEADS);
    attn_kernel<<<ga, 256, ATTN_SMEM>>>(x, G, S);

    dim3 gg(DM / 128, (B * S) / 128);
    out_gemm<<<gg, 256, GEMM_SMEM>>>(out);
}

// round 9
// speedup vs baseline: 1.5999x; 1.0123x over previous
#include <cuda_runtime.h>
#include <cuda_fp16.h>
#include <math.h>
#include <stdint.h>

#define NHEADS 16
#define HD 64
#define DM 1024
#define PDIM 64
#define MAXS 2048
#define MAXB 2
#define L2E 1.4426950408889634f
#define PSTR 68     // P row stride in fp16x2 words (272B = 17*16B): LDSM conflict-free
#define VSTR 36     // V row stride in fp16x2 words (144B = 9*16B):  LDSM conflict-free

// scratch (device globals — no runtime allocation)
__device__ float g_masses[MAXB * NHEADS * MAXS];                 // [B,H,S]
__device__ float g_invd[(size_t)MAXS * MAXS];                    // 1 / dist_sq_mod
__device__ uint32_t g_O[(size_t)MAXB * MAXS * DM / 2];           // attn out, fp16x2
__device__ uint32_t g_Wc[(size_t)DM * DM / 2];                   // W_out, fp16x2

// ---------------- helpers ----------------
__device__ __forceinline__ float ex2(float v) {
    float y;
    asm("ex2.approx.ftz.f32 %0, %1;" : "=f"(y) : "f"(v));
    return y;
}
__device__ __forceinline__ uint32_t smem_u32(const void* p) {
    uint32_t a;
    asm("{ .reg .u64 t; cvta.to.shared.u64 t, %1; cvt.u32.u64 %0, t; }" : "=r"(a) : "l"(p));
    return a;
}
// fp16 m16n8k16, fp32 accum
__device__ __forceinline__ void mma_f16(float* d, const uint32_t* a, const uint32_t* b) {
    asm volatile(
        "mma.sync.aligned.m16n8k16.row.col.f32.f16.f16.f32 "
        "{%0,%1,%2,%3}, {%4,%5,%6,%7}, {%8,%9}, {%0,%1,%2,%3};"
        : "+f"(d[0]), "+f"(d[1]), "+f"(d[2]), "+f"(d[3])
        : "r"(a[0]), "r"(a[1]), "r"(a[2]), "r"(a[3]), "r"(b[0]), "r"(b[1]));
}
__device__ __forceinline__ void ldsm_x4(uint32_t* r, uint32_t addr) {
    asm volatile("ldmatrix.sync.aligned.m8n8.x4.shared.b16 {%0,%1,%2,%3}, [%4];"
                 : "=r"(r[0]), "=r"(r[1]), "=r"(r[2]), "=r"(r[3]) : "r"(addr));
}
__device__ __forceinline__ void ldsm_x4_t(uint32_t* r, uint32_t addr) {
    asm volatile("ldmatrix.sync.aligned.m8n8.x4.trans.shared.b16 {%0,%1,%2,%3}, [%4];"
                 : "=r"(r[0]), "=r"(r[1]), "=r"(r[2]), "=r"(r[3]) : "r"(addr));
}

// ---------------------------------------------------------------------------
// Kernel 1: masses[b,h,s] = softplus( dot(xh[b,s,h,:], W_mass[h,:]) )
// ---------------------------------------------------------------------------
__global__ void mass_kernel(const float* __restrict__ x,
                            const float* __restrict__ Wm, int S) {
    int gw   = (blockIdx.x * 256 + threadIdx.x) >> 5;
    int lane = threadIdx.x & 31;
    int s = gw % S;
    int h = (gw / S) & (NHEADS - 1);
    int b = gw / (S * NHEADS);
    const float* xr = x + ((size_t)(b * S + s)) * DM + h * HD;
    float t = xr[lane] * Wm[h * HD + lane] + xr[lane + 32] * Wm[h * HD + lane + 32];
#pragma unroll
    for (int o = 16; o; o >>= 1) t += __shfl_xor_sync(0xffffffffu, t, o);
    if (lane == 0) {
        float m = (t > 20.f) ? t : log1pf(expf(t));
        g_masses[(b * NHEADS + h) * S + s] = m;
    }
}

// ---------------------------------------------------------------------------
// Kernel 1b: pre-convert W_out to fp16x2
// ---------------------------------------------------------------------------
__global__ void wcvt_kernel(const float* __restrict__ W) {
    int i = blockIdx.x * 256 + threadIdx.x;     // 8 floats / thread
    float4 v0 = *(const float4*)&W[(size_t)i * 8];
    float4 v1 = *(const float4*)&W[(size_t)i * 8 + 4];
    __half2 h0 = __floats2half2_rn(v0.x, v0.y);
    __half2 h1 = __floats2half2_rn(v0.z, v0.w);
    __half2 h2 = __floats2half2_rn(v1.x, v1.y);
    __half2 h3 = __floats2half2_rn(v1.z, v1.w);
    uint4 o;
    o.x = *(uint32_t*)&h0; o.y = *(uint32_t*)&h1;
    o.z = *(uint32_t*)&h2; o.w = *(uint32_t*)&h3;
    *(uint4*)&g_Wc[(size_t)i * 4] = o;
}

// ---------------------------------------------------------------------------
// Kernel 2: g_invd[i,j] = 1 / max( d2*(1+0.15*cos(sqrt(d2+1e-6))), 1e-6 )
// ---------------------------------------------------------------------------
__global__ void dist_kernel(const float* __restrict__ pos, int S) {
    __shared__ float Pi[PDIM][65];
    __shared__ float Pj[PDIM][65];
    int i0 = blockIdx.x * 64, j0 = blockIdx.y * 64;
    int tid = threadIdx.x;
#pragma unroll
    for (int v = 0; v < 16; v++) {
        int e = v * 256 + tid;
        int r = e >> 6, p = e & 63;
        Pi[p][r] = pos[(size_t)(i0 + r) * PDIM + p];
        Pj[p][r] = pos[(size_t)(j0 + r) * PDIM + p];
    }
    __syncthreads();
    int ty = tid >> 4, tx = tid & 15;
    float acc[4][4] = {};
#pragma unroll
    for (int p = 0; p < PDIM; p++) {
        float a[4], bb[4];
#pragma unroll
        for (int i = 0; i < 4; i++) a[i] = Pi[p][ty * 4 + i];
#pragma unroll
        for (int j = 0; j < 4; j++) bb[j] = Pj[p][tx * 4 + j];
#pragma unroll
        for (int i = 0; i < 4; i++)
#pragma unroll
            for (int j = 0; j < 4; j++) {
                float d = a[i] - bb[j];
                acc[i][j] = fmaf(d, d, acc[i][j]);
            }
    }
#pragma unroll
    for (int i = 0; i < 4; i++)
#pragma unroll
        for (int j = 0; j < 4; j++) {
            int ii = i0 + ty * 4 + i, jj = j0 + tx * 4 + j;
            float v = acc[i][j];
            float dn = sqrtf(v + 1e-6f);
            float d2 = v * (1.f + 0.15f * cosf(dn));
            d2 = fmaxf(d2, 1e-6f);
            g_invd[(size_t)ii * S + jj] = 1.0f / d2;
        }
}

// ---------------------------------------------------------------------------
// Kernel 3: attention, fp16 mma + ldmatrix. P' = exp(f-50) in (0,1].
// Phases per 128-j tile: [V fill + P gen] / sync / [LDSM+MMA] / sync.
// Warp = 16 rows x 64 cols; rowsum via ones-MMA on rounded fp16 P.
// ---------------------------------------------------------------------------
__global__ __launch_bounds__(256, 2)
void attn_kernel(const float* __restrict__ x,
                 const float* __restrict__ G, int S) {
    extern __shared__ char sm[];
    float* ms = (float*)sm;                           // [S]
    uint32_t* Ph = (uint32_t*)(sm + (size_t)S * 4);   // [128][PSTR] fp16x2 (j pairs)
    uint32_t* Vb = Ph + 128 * PSTR;                   // [128][VSTR] fp16x2 (n pairs)

    int bh = blockIdx.y;
    int b = bh >> 4, h = bh & 15;
    int i0 = blockIdx.x * 128;
    int tid = threadIdx.x;
    int w = tid >> 5, lane = tid & 31;
    int g = lane >> 2, t = lane & 3;
    int wm = 16 * w;
    int bS = b * S;

    const float* mrow = &g_masses[(b * NHEADS + h) * S];
    for (int i = tid; i < S; i += 256) ms[i] = mrow[i];
    __syncthreads();

    float coefl = fabsf(G[h]) * L2E;
    const float C50L = 50.0f * L2E;

    // LDSM base addresses (byte, shared space)
    uint32_t ph_b = smem_u32(Ph);
    uint32_t vb_b = smem_u32(Vb);
    uint32_t a_addr = ph_b + ((wm + (lane & 15)) * PSTR + ((lane >> 4) << 2)) * 4;
    uint32_t b_addr = vb_b + ((lane & 15) * VSTR + ((lane >> 4) << 2)) * 4;

    float acc[8][4] = {};
    float sacc[4] = {};
    int niter = S >> 7;

    for (int it = 0; it < niter; it++) {
        int jt = it << 7;

        // ---- V fill: Vb[j][n] fp16 rows (n contiguous); 2 slots/thread
#pragma unroll
        for (int v = 0; v < 2; v++) {
            int slot = v * 256 + tid;
            int j = slot >> 2, n16 = slot & 3;
            const float* xp = &x[((size_t)(bS + jt + j)) * DM + h * HD + n16 * 16];
            float4 f0 = *(const float4*)xp;
            float4 f1 = *(const float4*)(xp + 4);
            float4 f2 = *(const float4*)(xp + 8);
            float4 f3 = *(const float4*)(xp + 12);
            __half2 q0 = __floats2half2_rn(f0.x, f0.y), q1 = __floats2half2_rn(f0.z, f0.w);
            __half2 q2 = __floats2half2_rn(f1.x, f1.y), q3 = __floats2half2_rn(f1.z, f1.w);
            __half2 q4 = __floats2half2_rn(f2.x, f2.y), q5 = __floats2half2_rn(f2.z, f2.w);
            __half2 q6 = __floats2half2_rn(f3.x, f3.y), q7 = __floats2half2_rn(f3.z, f3.w);
            uint4 o0, o1;
            o0.x = *(uint32_t*)&q0; o0.y = *(uint32_t*)&q1;
            o0.z = *(uint32_t*)&q2; o0.w = *(uint32_t*)&q3;
            o1.x = *(uint32_t*)&q4; o1.y = *(uint32_t*)&q5;
            o1.z = *(uint32_t*)&q6; o1.w = *(uint32_t*)&q7;
            uint32_t* dst = Vb + j * VSTR + n16 * 8;
            *(uint4*)dst = o0;
            *(uint4*)(dst + 4) = o1;
        }
        // ---- P gen: row per (v,w); 4 cols/thread
#pragma unroll
        for (int v = 0; v < 16; v++) {
            int r = v * 8 + w;
            float cm = coefl * ms[i0 + r];
            float4 dv = *(const float4*)&g_invd[(size_t)(i0 + r) * S + jt + 4 * lane];
            float4 mv = *(const float4*)&ms[jt + 4 * lane];
            float e0 = ex2(fminf(cm * mv.x * dv.x, C50L) - C50L);
            float e1 = ex2(fminf(cm * mv.y * dv.y, C50L) - C50L);
            float e2 = ex2(fminf(cm * mv.z * dv.z, C50L) - C50L);
            float e3 = ex2(fminf(cm * mv.w * dv.w, C50L) - C50L);
            __half2 p0 = __floats2half2_rn(e0, e1);
            __half2 p1 = __floats2half2_rn(e2, e3);
            uint2 o;
            o.x = *(uint32_t*)&p0; o.y = *(uint32_t*)&p1;
            *(uint2*)&Ph[r * PSTR + 2 * lane] = o;
        }
        __syncthreads();   // tiles ready

        // ---- LDSM + MMA: 8 k16-chunks
#pragma unroll
        for (int kc = 0; kc < 8; kc++) {
            uint32_t a[4];
            ldsm_x4(a, a_addr + kc * 32);                 // +8 words per chunk
            uint32_t ones[2] = {0x3C003C00u, 0x3C003C00u};
            mma_f16(sacc, a, ones);                       // rowsum
#pragma unroll
            for (int nt2 = 0; nt2 < 4; nt2++) {
                uint32_t bf[4];
                ldsm_x4_t(bf, b_addr + kc * 16 * VSTR * 4 + nt2 * 32);
                mma_f16(acc[2 * nt2], a, bf);
                mma_f16(acc[2 * nt2 + 1], a, bf + 2);
            }
        }
        __syncthreads();   // MMA reads done before next fill
    }

    float r0 = 1.0f / sacc[0];
    float r1 = 1.0f / sacc[2];
    size_t w0 = (((size_t)(bS + i0 + wm + g)) * DM + h * HD) >> 1;   // fp16x2 words
    size_t w1 = w0 + (size_t)4 * DM;                                  // +8 rows
#pragma unroll
    for (int nt = 0; nt < 8; nt++) {
        __half2 o0 = __floats2half2_rn(acc[nt][0] * r0, acc[nt][1] * r0);
        __half2 o1 = __floats2half2_rn(acc[nt][2] * r1, acc[nt][3] * r1);
        g_O[w0 + nt * 4 + t] = *(uint32_t*)&o0;
        g_O[w1 + nt * 4 + t] = *(uint32_t*)&o1;
    }
}

// ---------------------------------------------------------------------------
// Kernel 4: Y = O @ Wc^T, fp16 mma.sync m16n8k16, cp.async double-buffered.
// Chunk = 64 k-halfs = 32 fp16x2 words (same layout/swizzle math as tf32 ver).
// ---------------------------------------------------------------------------
__global__ __launch_bounds__(256, 2)
void out_gemm(float* __restrict__ Y) {
    extern __shared__ uint32_t sm_g[];
    uint32_t* As = sm_g;                 // [2][128][32] fp16x2 words
    uint32_t* Bs = sm_g + 2 * 128 * 32;

    int n0 = blockIdx.y * 128, j0 = blockIdx.x * 128;
    int tid = threadIdx.x;
    int w = tid >> 5, lane = tid & 31;
    int g = lane >> 2, t = lane & 3;
    int wm = (w >> 2) * 64, wn = (w & 3) * 32;
    int swz = g << 2;

    float acc[4][4][4] = {};

    int cr[4], cc[4];
#pragma unroll
    for (int v = 0; v < 4; v++) {
        int idx4 = v * 256 + tid;
        cr[v] = idx4 >> 3;
        cc[v] = (idx4 & 7) * 4;
    }

#define OG_ISSUE(buf, k0w)                                                       \
    do {                                                                         \
        _Pragma("unroll")                                                        \
        for (int v = 0; v < 4; v++) {                                            \
            int r = cr[v], c = cc[v];                                            \
            int so = r * 32 + (c ^ ((r & 7) << 2));                              \
            uint32_t dA = (uint32_t)__cvta_generic_to_shared(&As[(buf)*4096 + so]); \
            const uint32_t* sA = &g_O[(size_t)(n0 + r) * (DM / 2) + (k0w) + c];  \
            asm volatile("cp.async.cg.shared.global [%0], [%1], 16;" ::"r"(dA), "l"(sA)); \
            uint32_t dB = (uint32_t)__cvta_generic_to_shared(&Bs[(buf)*4096 + so]); \
            const uint32_t* sB = &g_Wc[(size_t)(j0 + r) * (DM / 2) + (k0w) + c]; \
            asm volatile("cp.async.cg.shared.global [%0], [%1], 16;" ::"r"(dB), "l"(sB)); \
        }                                                                        \
        asm volatile("cp.async.commit_group;");                                  \
    } while (0)

    OG_ISSUE(0, 0);

    for (int ki = 0; ki < DM / 64; ki++) {
        asm volatile("cp.async.wait_group 0;");
        __syncthreads();
        if (ki + 1 < DM / 64) OG_ISSUE((ki + 1) & 1, (ki + 1) * 32);

        const uint32_t* Ab = &As[(ki & 1) * 4096];
        const uint32_t* Bb = &Bs[(ki & 1) * 4096];
#pragma unroll
        for (int ks = 0; ks < 4; ks++) {
            int k = ks * 8;
            uint32_t a[4][4], bf[4][2];
#pragma unroll
            for (int mt = 0; mt < 4; mt++) {
                int r = wm + mt * 16 + g;
                a[mt][0] = Ab[r * 32 + ((k + t) ^ swz)];
                a[mt][1] = Ab[(r + 8) * 32 + ((k + t) ^ swz)];
                a[mt][2] = Ab[r * 32 + ((k + t + 4) ^ swz)];
                a[mt][3] = Ab[(r + 8) * 32 + ((k + t + 4) ^ swz)];
            }
#pragma unroll
            for (int nt = 0; nt < 4; nt++) {
                int r = wn + nt * 8 + g;
                bf[nt][0] = Bb[r * 32 + ((k + t) ^ swz)];
                bf[nt][1] = Bb[r * 32 + ((k + t + 4) ^ swz)];
            }
#pragma unroll
            for (int mt = 0; mt < 4; mt++)
#pragma unroll
                for (int nt = 0; nt < 4; nt++)
                    mma_f16(acc[mt][nt], a[mt], bf[nt]);
        }
    }
#pragma unroll
    for (int mt = 0; mt < 4; mt++) {
        int m = n0 + wm + mt * 16 + g;
#pragma unroll
        for (int nt = 0; nt < 4; nt++) {
            int j = j0 + wn + nt * 8 + 2 * t;
            float2 v0, v1;
            v0.x = acc[mt][nt][0]; v0.y = acc[mt][nt][1];
            v1.x = acc[mt][nt][2]; v1.y = acc[mt][nt][3];
            *(float2*)&Y[(size_t)m * DM + j] = v0;
            *(float2*)&Y[(size_t)(m + 8) * DM + j] = v1;
        }
    }
}

// ---------------------------------------------------------------------------
extern "C" void kernel_launch(void* const* d_in, const int* in_sizes, int n_in,
                              void* d_out, int out_size) {
    const float* x   = (const float*)d_in[0];   // [B,S,1024]
    const float* pos = (const float*)d_in[1];   // [S,64]
    const float* Wm  = (const float*)d_in[2];   // [16,64]
    const float* G   = (const float*)d_in[3];   // [16]
    const float* Wo  = (const float*)d_in[4];   // [1024,1024]
    float* out = (float*)d_out;                 // [B,S,1024]

    int S = in_sizes[1] / PDIM;
    int B = in_sizes[0] / (S * DM);

    int ATTN_SMEM = S * 4 + 128 * PSTR * 4 + 128 * VSTR * 4;
    static const int GEMM_SMEM = 4 * 128 * 32 * 4;
    cudaFuncSetAttribute(attn_kernel, cudaFuncAttributeMaxDynamicSharedMemorySize, ATTN_SMEM);
    cudaFuncSetAttribute(out_gemm, cudaFuncAttributeMaxDynamicSharedMemorySize, GEMM_SMEM);

    int nwarps = B * NHEADS * S;
    mass_kernel<<<nwarps / 8, 256>>>(x, Wm, S);

    wcvt_kernel<<<DM * DM / 2048, 256>>>(Wo);

    dim3 gd(S / 64, S / 64);
    dist_kernel<<<gd, 256>>>(pos, S);

    dim3 ga(S / 128, B * NHEADS);
    attn_kernel<<<ga, 256, ATTN_SMEM>>>(x, G, S);

    dim3 gg(DM / 128, (B * S) / 128);
    out_gemm<<<gg, 256, GEMM_SMEM>>>(out);
}

// round 10
// speedup vs baseline: 1.8014x; 1.1259x over previous
#include <cuda_runtime.h>
#include <cuda_fp16.h>
#include <math.h>
#include <stdint.h>

#define NHEADS 16
#define HD 64
#define DM 1024
#define PDIM 64
#define MAXS 2048
#define MAXB 2
#define L2E 1.4426950408889634f
#define PSTR 68     // P smem row stride (fp16x2 words); a-frag banks 4g+t distinct
#define VSTR 72     // V smem row stride (fp16x2 words); b-frag banks conflict-free

// scratch (device globals — no runtime allocation)
__device__ float g_masses[MAXB * NHEADS * MAXS];                 // [B,H,S]
__device__ float g_invd[(size_t)MAXS * MAXS];                    // 1 / dist_sq_mod
__device__ uint32_t g_O[(size_t)MAXB * MAXS * DM / 2];           // attn out, fp16x2
__device__ uint32_t g_Wc[(size_t)DM * DM / 2];                   // W_out, fp16x2

// ---------------- helpers ----------------
__device__ __forceinline__ float ex2(float v) {
    float y;
    asm("ex2.approx.ftz.f32 %0, %1;" : "=f"(y) : "f"(v));
    return y;
}
// fp16 m16n8k16, fp32 accum
__device__ __forceinline__ void mma_f16(float* d, const uint32_t* a, const uint32_t* b) {
    asm volatile(
        "mma.sync.aligned.m16n8k16.row.col.f32.f16.f16.f32 "
        "{%0,%1,%2,%3}, {%4,%5,%6,%7}, {%8,%9}, {%0,%1,%2,%3};"
        : "+f"(d[0]), "+f"(d[1]), "+f"(d[2]), "+f"(d[3])
        : "r"(a[0]), "r"(a[1]), "r"(a[2]), "r"(a[3]), "r"(b[0]), "r"(b[1]));
}

// ---------------------------------------------------------------------------
// Kernel 1: masses[b,h,s] = softplus( dot(xh[b,s,h,:], W_mass[h,:]) )
// ---------------------------------------------------------------------------
__global__ void mass_kernel(const float* __restrict__ x,
                            const float* __restrict__ Wm, int S) {
    int gw   = (blockIdx.x * 256 + threadIdx.x) >> 5;
    int lane = threadIdx.x & 31;
    int s = gw % S;
    int h = (gw / S) & (NHEADS - 1);
    int b = gw / (S * NHEADS);
    const float* xr = x + ((size_t)(b * S + s)) * DM + h * HD;
    float t = xr[lane] * Wm[h * HD + lane] + xr[lane + 32] * Wm[h * HD + lane + 32];
#pragma unroll
    for (int o = 16; o; o >>= 1) t += __shfl_xor_sync(0xffffffffu, t, o);
    if (lane == 0) {
        float m = (t > 20.f) ? t : log1pf(expf(t));
        g_masses[(b * NHEADS + h) * S + s] = m;
    }
}

// ---------------------------------------------------------------------------
// Kernel 1b: pre-convert W_out to fp16x2
// ---------------------------------------------------------------------------
__global__ void wcvt_kernel(const float* __restrict__ W) {
    int i = blockIdx.x * 256 + threadIdx.x;     // 8 floats / thread
    float4 v0 = *(const float4*)&W[(size_t)i * 8];
    float4 v1 = *(const float4*)&W[(size_t)i * 8 + 4];
    __half2 h0 = __floats2half2_rn(v0.x, v0.y);
    __half2 h1 = __floats2half2_rn(v0.z, v0.w);
    __half2 h2 = __floats2half2_rn(v1.x, v1.y);
    __half2 h3 = __floats2half2_rn(v1.z, v1.w);
    uint4 o;
    o.x = *(uint32_t*)&h0; o.y = *(uint32_t*)&h1;
    o.z = *(uint32_t*)&h2; o.w = *(uint32_t*)&h3;
    *(uint4*)&g_Wc[(size_t)i * 4] = o;
}

// ---------------------------------------------------------------------------
// Kernel 2: g_invd[i,j] = 1 / max( d2*(1+0.15*cos(sqrt(d2+1e-6))), 1e-6 )
// ---------------------------------------------------------------------------
__global__ void dist_kernel(const float* __restrict__ pos, int S) {
    __shared__ float Pi[PDIM][65];
    __shared__ float Pj[PDIM][65];
    int i0 = blockIdx.x * 64, j0 = blockIdx.y * 64;
    int tid = threadIdx.x;
#pragma unroll
    for (int v = 0; v < 16; v++) {
        int e = v * 256 + tid;
        int r = e >> 6, p = e & 63;
        Pi[p][r] = pos[(size_t)(i0 + r) * PDIM + p];
        Pj[p][r] = pos[(size_t)(j0 + r) * PDIM + p];
    }
    __syncthreads();
    int ty = tid >> 4, tx = tid & 15;
    float acc[4][4] = {};
#pragma unroll
    for (int p = 0; p < PDIM; p++) {
        float a[4], bb[4];
#pragma unroll
        for (int i = 0; i < 4; i++) a[i] = Pi[p][ty * 4 + i];
#pragma unroll
        for (int j = 0; j < 4; j++) bb[j] = Pj[p][tx * 4 + j];
#pragma unroll
        for (int i = 0; i < 4; i++)
#pragma unroll
            for (int j = 0; j < 4; j++) {
                float d = a[i] - bb[j];
                acc[i][j] = fmaf(d, d, acc[i][j]);
            }
    }
#pragma unroll
    for (int i = 0; i < 4; i++)
#pragma unroll
        for (int j = 0; j < 4; j++) {
            int ii = i0 + ty * 4 + i, jj = j0 + tx * 4 + j;
            float v = acc[i][j];
            float dn = sqrtf(v + 1e-6f);
            float d2 = v * (1.f + 0.15f * cosf(dn));
            d2 = fmaxf(d2, 1e-6f);
            g_invd[(size_t)ii * S + jj] = 1.0f / d2;
        }
}

// ---------------------------------------------------------------------------
// Kernel 3: attention in fp16 (P' = exp(f-50), range (0,1]); R8 structure:
// [fill V + gen P] / sync / [MMA] / sync. Warp = 16 rows x 64 cols.
// Rowsum via ones-MMA on the ROUNDED fp16 P. Output g_O written fp16x2.
// ---------------------------------------------------------------------------
__global__ __launch_bounds__(256, 2)
void attn_kernel(const float* __restrict__ x,
                 const float* __restrict__ G, int S) {
    extern __shared__ char sm[];
    float* ms = (float*)sm;                          // [S] masses for this (b,h)
    uint32_t* Ph = (uint32_t*)(sm + (size_t)S * 4);  // [128][PSTR] fp16x2 (j pairs)
    uint32_t* Vb = Ph + 128 * PSTR;                  // [64][VSTR]  fp16x2 (k pairs)

    int bh = blockIdx.y;
    int b = bh >> 4, h = bh & 15;
    int i0 = blockIdx.x * 128;
    int tid = threadIdx.x;
    int w = tid >> 5, lane = tid & 31;
    int g = lane >> 2, t = lane & 3;
    int wm = 16 * w;
    int bS = b * S;

    const float* mrow = &g_masses[(b * NHEADS + h) * S];
    for (int i = tid; i < S; i += 256) ms[i] = mrow[i];
    __syncthreads();

    float coefl = fabsf(G[h]) * L2E;
    const float C50L = 50.0f * L2E;

    float acc[8][4] = {};
    float sacc[4] = {};
    int niter = S >> 7;

    for (int it = 0; it < niter; it++) {
        int jt = it << 7;

        // ---- V fill: Vb[k2][n] = {V[2k2][n], V[2k2+1][n]} fp16x2
#pragma unroll
        for (int v4 = 0; v4 < 4; v4++) {
            int slot = v4 * 256 + tid;
            int n4 = slot & 15, k2 = slot >> 4;
            const float* xp = &x[((size_t)(bS + jt + 2 * k2)) * DM + h * HD + n4 * 4];
            float4 r0 = *(const float4*)xp;
            float4 r1 = *(const float4*)(xp + DM);
            __half2 h0 = __floats2half2_rn(r0.x, r1.x);
            __half2 h1 = __floats2half2_rn(r0.y, r1.y);
            __half2 h2 = __floats2half2_rn(r0.z, r1.z);
            __half2 h3 = __floats2half2_rn(r0.w, r1.w);
            uint4 o;
            o.x = *(uint32_t*)&h0; o.y = *(uint32_t*)&h1;
            o.z = *(uint32_t*)&h2; o.w = *(uint32_t*)&h3;
            *(uint4*)&Vb[k2 * VSTR + n4 * 4] = o;
        }
        // ---- P gen: row per (v,w); 4 cols/thread; P' = exp2(min(fL,C)-C)
#pragma unroll
        for (int v = 0; v < 16; v++) {
            int r = v * 8 + w;
            float cm = coefl * ms[i0 + r];
            float4 dv = *(const float4*)&g_invd[(size_t)(i0 + r) * S + jt + 4 * lane];
            float4 mv = *(const float4*)&ms[jt + 4 * lane];
            float e0 = ex2(fminf(cm * mv.x * dv.x, C50L) - C50L);
            float e1 = ex2(fminf(cm * mv.y * dv.y, C50L) - C50L);
            float e2 = ex2(fminf(cm * mv.z * dv.z, C50L) - C50L);
            float e3 = ex2(fminf(cm * mv.w * dv.w, C50L) - C50L);
            __half2 p0 = __floats2half2_rn(e0, e1);
            __half2 p1 = __floats2half2_rn(e2, e3);
            uint2 o;
            o.x = *(uint32_t*)&p0; o.y = *(uint32_t*)&p1;
            *(uint2*)&Ph[r * PSTR + 2 * lane] = o;
        }
        __syncthreads();   // tiles ready

        // ---- MMA: 8 k16-chunks x (8 n-tiles + rowsum)
#pragma unroll
        for (int kc = 0; kc < 8; kc++) {
            uint32_t a[4];
            int ra = (wm + g) * PSTR + 8 * kc + t;
            int rb = ra + 8 * PSTR;
            a[0] = Ph[ra];     a[1] = Ph[rb];
            a[2] = Ph[ra + 4]; a[3] = Ph[rb + 4];
#pragma unroll
            for (int nt = 0; nt < 8; nt++) {
                uint32_t br[2];
                br[0] = Vb[(8 * kc + t) * VSTR + nt * 8 + g];
                br[1] = Vb[(8 * kc + t + 4) * VSTR + nt * 8 + g];
                mma_f16(acc[nt], a, br);
            }
            uint32_t ones[2] = {0x3C003C00u, 0x3C003C00u};
            mma_f16(sacc, a, ones);
        }
        __syncthreads();   // MMA reads done before next fill
    }

    float r0 = 1.0f / sacc[0];
    float r1 = 1.0f / sacc[2];
    size_t w0 = (((size_t)(bS + i0 + wm + g)) * DM + h * HD) >> 1;   // fp16x2 words
    size_t w1 = w0 + (size_t)4 * DM;                                  // +8 rows
#pragma unroll
    for (int nt = 0; nt < 8; nt++) {
        __half2 o0 = __floats2half2_rn(acc[nt][0] * r0, acc[nt][1] * r0);
        __half2 o1 = __floats2half2_rn(acc[nt][2] * r1, acc[nt][3] * r1);
        g_O[w0 + nt * 4 + t] = *(uint32_t*)&o0;
        g_O[w1 + nt * 4 + t] = *(uint32_t*)&o1;
    }
}

// ---------------------------------------------------------------------------
// Kernel 4: Y = O @ Wc^T, fp16 mma.sync m16n8k16, cp.async double-buffered.
// Chunk = 64 k-halfs = 32 fp16x2 words.
// ---------------------------------------------------------------------------
__global__ __launch_bounds__(256, 2)
void out_gemm(float* __restrict__ Y) {
    extern __shared__ uint32_t sm_g[];
    uint32_t* As = sm_g;                 // [2][128][32] fp16x2 words
    uint32_t* Bs = sm_g + 2 * 128 * 32;

    int n0 = blockIdx.y * 128, j0 = blockIdx.x * 128;
    int tid = threadIdx.x;
    int w = tid >> 5, lane = tid & 31;
    int g = lane >> 2, t = lane & 3;
    int wm = (w >> 2) * 64, wn = (w & 3) * 32;
    int swz = g << 2;

    float acc[4][4][4] = {};

    int cr[4], cc[4];
#pragma unroll
    for (int v = 0; v < 4; v++) {
        int idx4 = v * 256 + tid;
        cr[v] = idx4 >> 3;
        cc[v] = (idx4 & 7) * 4;
    }

#define OG_ISSUE(buf, k0w)                                                       \
    do {                                                                         \
        _Pragma("unroll")                                                        \
        for (int v = 0; v < 4; v++) {                                            \
            int r = cr[v], c = cc[v];                                            \
            int so = r * 32 + (c ^ ((r & 7) << 2));                              \
            uint32_t dA = (uint32_t)__cvta_generic_to_shared(&As[(buf)*4096 + so]); \
            const uint32_t* sA = &g_O[(size_t)(n0 + r) * (DM / 2) + (k0w) + c];  \
            asm volatile("cp.async.cg.shared.global [%0], [%1], 16;" ::"r"(dA), "l"(sA)); \
            uint32_t dB = (uint32_t)__cvta_generic_to_shared(&Bs[(buf)*4096 + so]); \
            const uint32_t* sB = &g_Wc[(size_t)(j0 + r) * (DM / 2) + (k0w) + c]; \
            asm volatile("cp.async.cg.shared.global [%0], [%1], 16;" ::"r"(dB), "l"(sB)); \
        }                                                                        \
        asm volatile("cp.async.commit_group;");                                  \
    } while (0)

    OG_ISSUE(0, 0);

    for (int ki = 0; ki < DM / 64; ki++) {
        asm volatile("cp.async.wait_group 0;");
        __syncthreads();
        if (ki + 1 < DM / 64) OG_ISSUE((ki + 1) & 1, (ki + 1) * 32);

        const uint32_t* Ab = &As[(ki & 1) * 4096];
        const uint32_t* Bb = &Bs[(ki & 1) * 4096];
#pragma unroll
        for (int ks = 0; ks < 4; ks++) {
            int k = ks * 8;
            uint32_t a[4][4], bf[4][2];
#pragma unroll
            for (int mt = 0; mt < 4; mt++) {
                int r = wm + mt * 16 + g;
                a[mt][0] = Ab[r * 32 + ((k + t) ^ swz)];
                a[mt][1] = Ab[(r + 8) * 32 + ((k + t) ^ swz)];
                a[mt][2] = Ab[r * 32 + ((k + t + 4) ^ swz)];
                a[mt][3] = Ab[(r + 8) * 32 + ((k + t + 4) ^ swz)];
            }
#pragma unroll
            for (int nt = 0; nt < 4; nt++) {
                int r = wn + nt * 8 + g;
                bf[nt][0] = Bb[r * 32 + ((k + t) ^ swz)];
                bf[nt][1] = Bb[r * 32 + ((k + t + 4) ^ swz)];
            }
#pragma unroll
            for (int mt = 0; mt < 4; mt++)
#pragma unroll
                for (int nt = 0; nt < 4; nt++)
                    mma_f16(acc[mt][nt], a[mt], bf[nt]);
        }
    }
#pragma unroll
    for (int mt = 0; mt < 4; mt++) {
        int m = n0 + wm + mt * 16 + g;
#pragma unroll
        for (int nt = 0; nt < 4; nt++) {
            int j = j0 + wn + nt * 8 + 2 * t;
            float2 v0, v1;
            v0.x = acc[mt][nt][0]; v0.y = acc[mt][nt][1];
            v1.x = acc[mt][nt][2]; v1.y = acc[mt][nt][3];
            *(float2*)&Y[(size_t)m * DM + j] = v0;
            *(float2*)&Y[(size_t)(m + 8) * DM + j] = v1;
        }
    }
}

// ---------------------------------------------------------------------------
extern "C" void kernel_launch(void* const* d_in, const int* in_sizes, int n_in,
                              void* d_out, int out_size) {
    const float* x   = (const float*)d_in[0];   // [B,S,1024]
    const float* pos = (const float*)d_in[1];   // [S,64]
    const float* Wm  = (const float*)d_in[2];   // [16,64]
    const float* G   = (const float*)d_in[3];   // [16]
    const float* Wo  = (const float*)d_in[4];   // [1024,1024]
    float* out = (float*)d_out;                 // [B,S,1024]

    int S = in_sizes[1] / PDIM;
    int B = in_sizes[0] / (S * DM);

    int ATTN_SMEM = S * 4 + 128 * PSTR * 4 + 64 * VSTR * 4;
    static const int GEMM_SMEM = 4 * 128 * 32 * 4;
    cudaFuncSetAttribute(attn_kernel, cudaFuncAttributeMaxDynamicSharedMemorySize, ATTN_SMEM);
    cudaFuncSetAttribute(out_gemm, cudaFuncAttributeMaxDynamicSharedMemorySize, GEMM_SMEM);

    int nwarps = B * NHEADS * S;
    mass_kernel<<<nwarps / 8, 256>>>(x, Wm, S);

    wcvt_kernel<<<DM * DM / 2048, 256>>>(Wo);

    dim3 gd(S / 64, S / 64);
    dist_kernel<<<gd, 256>>>(pos, S);

    dim3 ga(S / 128, B * NHEADS);
    attn_kernel<<<ga, 256, ATTN_SMEM>>>(x, G, S);

    dim3 gg(DM / 128, (B * S) / 128);
    out_gemm<<<gg, 256, GEMM_SMEM>>>(out);
}

// round 11
// speedup vs baseline: 1.8403x; 1.0216x over previous
#include <cuda_runtime.h>
#include <cuda_fp16.h>
#include <math.h>
#include <stdint.h>

#define NHEADS 16
#define HD 64
#define DM 1024
#define PDIM 64
#define MAXS 2048
#define MAXB 2
#define L2E 1.4426950408889634f
#define PSTR 68     // P smem row stride (fp16x2 words); a-frag banks 4g+t distinct
#define VSTR 72     // V smem row stride (fp16x2 words); b-frag banks conflict-free

// scratch (device globals — no runtime allocation)
__device__ float g_masses[MAXB * NHEADS * MAXS];                 // [B,H,S]
__device__ float g_invd[(size_t)MAXS * MAXS];                    // 1 / dist_sq_mod
__device__ uint32_t g_O[(size_t)MAXB * MAXS * DM / 2];           // attn out, fp16x2
__device__ uint32_t g_Wc[(size_t)DM * DM / 2];                   // W_out, fp16x2

// ---------------- helpers ----------------
__device__ __forceinline__ float ex2(float v) {
    float y;
    asm("ex2.approx.ftz.f32 %0, %1;" : "=f"(y) : "f"(v));
    return y;
}
// fp16 m16n8k16, fp32 accum
__device__ __forceinline__ void mma_f16(float* d, const uint32_t* a, const uint32_t* b) {
    asm volatile(
        "mma.sync.aligned.m16n8k16.row.col.f32.f16.f16.f32 "
        "{%0,%1,%2,%3}, {%4,%5,%6,%7}, {%8,%9}, {%0,%1,%2,%3};"
        : "+f"(d[0]), "+f"(d[1]), "+f"(d[2]), "+f"(d[3])
        : "r"(a[0]), "r"(a[1]), "r"(a[2]), "r"(a[3]), "r"(b[0]), "r"(b[1]));
}

// ---------------------------------------------------------------------------
// Kernel 1: masses[b,h,s] = softplus( dot(xh[b,s,h,:], W_mass[h,:]) )
// ---------------------------------------------------------------------------
__global__ void mass_kernel(const float* __restrict__ x,
                            const float* __restrict__ Wm, int S) {
    int gw   = (blockIdx.x * 256 + threadIdx.x) >> 5;
    int lane = threadIdx.x & 31;
    int s = gw % S;
    int h = (gw / S) & (NHEADS - 1);
    int b = gw / (S * NHEADS);
    const float* xr = x + ((size_t)(b * S + s)) * DM + h * HD;
    float t = xr[lane] * Wm[h * HD + lane] + xr[lane + 32] * Wm[h * HD + lane + 32];
#pragma unroll
    for (int o = 16; o; o >>= 1) t += __shfl_xor_sync(0xffffffffu, t, o);
    if (lane == 0) {
        float m = (t > 20.f) ? t : log1pf(expf(t));
        g_masses[(b * NHEADS + h) * S + s] = m;
    }
}

// ---------------------------------------------------------------------------
// Kernel 1b: pre-convert W_out to fp16x2
// ---------------------------------------------------------------------------
__global__ void wcvt_kernel(const float* __restrict__ W) {
    int i = blockIdx.x * 256 + threadIdx.x;     // 8 floats / thread
    float4 v0 = *(const float4*)&W[(size_t)i * 8];
    float4 v1 = *(const float4*)&W[(size_t)i * 8 + 4];
    __half2 h0 = __floats2half2_rn(v0.x, v0.y);
    __half2 h1 = __floats2half2_rn(v0.z, v0.w);
    __half2 h2 = __floats2half2_rn(v1.x, v1.y);
    __half2 h3 = __floats2half2_rn(v1.z, v1.w);
    uint4 o;
    o.x = *(uint32_t*)&h0; o.y = *(uint32_t*)&h1;
    o.z = *(uint32_t*)&h2; o.w = *(uint32_t*)&h3;
    *(uint4*)&g_Wc[(size_t)i * 4] = o;
}

// ---------------------------------------------------------------------------
// Kernel 2: g_invd[i,j] = 1 / max( d2*(1+0.15*cos(sqrt(d2+1e-6))), 1e-6 )
// ---------------------------------------------------------------------------
__global__ void dist_kernel(const float* __restrict__ pos, int S) {
    __shared__ float Pi[PDIM][65];
    __shared__ float Pj[PDIM][65];
    int i0 = blockIdx.x * 64, j0 = blockIdx.y * 64;
    int tid = threadIdx.x;
#pragma unroll
    for (int v = 0; v < 16; v++) {
        int e = v * 256 + tid;
        int r = e >> 6, p = e & 63;
        Pi[p][r] = pos[(size_t)(i0 + r) * PDIM + p];
        Pj[p][r] = pos[(size_t)(j0 + r) * PDIM + p];
    }
    __syncthreads();
    int ty = tid >> 4, tx = tid & 15;
    float acc[4][4] = {};
#pragma unroll
    for (int p = 0; p < PDIM; p++) {
        float a[4], bb[4];
#pragma unroll
        for (int i = 0; i < 4; i++) a[i] = Pi[p][ty * 4 + i];
#pragma unroll
        for (int j = 0; j < 4; j++) bb[j] = Pj[p][tx * 4 + j];
#pragma unroll
        for (int i = 0; i < 4; i++)
#pragma unroll
            for (int j = 0; j < 4; j++) {
                float d = a[i] - bb[j];
                acc[i][j] = fmaf(d, d, acc[i][j]);
            }
    }
#pragma unroll
    for (int i = 0; i < 4; i++)
#pragma unroll
        for (int j = 0; j < 4; j++) {
            int ii = i0 + ty * 4 + i, jj = j0 + tx * 4 + j;
            float v = acc[i][j];
            float dn = sqrtf(v + 1e-6f);
            float d2 = v * (1.f + 0.15f * cosf(dn));
            d2 = fmaxf(d2, 1e-6f);
            g_invd[(size_t)ii * S + jj] = 1.0f / d2;
        }
}

// ---------------------------------------------------------------------------
// attn device pieces (identical math/layout to the 130us version)
// ---------------------------------------------------------------------------
__device__ __forceinline__ void v_fill(uint32_t* __restrict__ Vb,
                                       const float* __restrict__ x,
                                       int bS, int jt, int h, int tid) {
#pragma unroll
    for (int v4 = 0; v4 < 4; v4++) {
        int slot = v4 * 256 + tid;
        int n4 = slot & 15, k2 = slot >> 4;
        const float* xp = &x[((size_t)(bS + jt + 2 * k2)) * DM + h * HD + n4 * 4];
        float4 r0 = *(const float4*)xp;
        float4 r1 = *(const float4*)(xp + DM);
        __half2 h0 = __floats2half2_rn(r0.x, r1.x);
        __half2 h1 = __floats2half2_rn(r0.y, r1.y);
        __half2 h2 = __floats2half2_rn(r0.z, r1.z);
        __half2 h3 = __floats2half2_rn(r0.w, r1.w);
        uint4 o;
        o.x = *(uint32_t*)&h0; o.y = *(uint32_t*)&h1;
        o.z = *(uint32_t*)&h2; o.w = *(uint32_t*)&h3;
        *(uint4*)&Vb[k2 * VSTR + n4 * 4] = o;
    }
}
__device__ __forceinline__ void p_gen(uint32_t* __restrict__ Ph,
                                      const float* __restrict__ ms,
                                      int i0, int jt, int S, float coefl,
                                      int w, int lane) {
    const float C50L = 50.0f * L2E;
#pragma unroll
    for (int v = 0; v < 16; v++) {
        int r = v * 8 + w;
        float cm = coefl * ms[i0 + r];
        float4 dv = *(const float4*)&g_invd[(size_t)(i0 + r) * S + jt + 4 * lane];
        float4 mv = *(const float4*)&ms[jt + 4 * lane];
        float e0 = ex2(fminf(cm * mv.x * dv.x, C50L) - C50L);
        float e1 = ex2(fminf(cm * mv.y * dv.y, C50L) - C50L);
        float e2 = ex2(fminf(cm * mv.z * dv.z, C50L) - C50L);
        float e3 = ex2(fminf(cm * mv.w * dv.w, C50L) - C50L);
        __half2 p0 = __floats2half2_rn(e0, e1);
        __half2 p1 = __floats2half2_rn(e2, e3);
        uint2 o;
        o.x = *(uint32_t*)&p0; o.y = *(uint32_t*)&p1;
        *(uint2*)&Ph[r * PSTR + 2 * lane] = o;
    }
}

// ---------------------------------------------------------------------------
// Kernel 3: attention in fp16 (P' = exp(f-50)); DOUBLE-BUFFERED P/V tiles,
// ONE __syncthreads per j-tile. Per-warp order: MMA(it) -> fill/gen(it+1)
// -> sync. gen(it+1) targets the buffer last read by MMA(it-1), which all
// warps completed before the previous sync. Warp = 16 rows x 64 cols;
// rowsum via ones-MMA on rounded fp16 P.
// ---------------------------------------------------------------------------
__global__ __launch_bounds__(256, 2)
void attn_kernel(const float* __restrict__ x,
                 const float* __restrict__ G, int S) {
    extern __shared__ char sm[];
    float* ms = (float*)sm;                          // [S]
    uint32_t* Pbuf = (uint32_t*)(sm + (size_t)S * 4);   // 2 x [128][PSTR]
    uint32_t* Vbuf = Pbuf + 2 * 128 * PSTR;             // 2 x [64][VSTR]

    int bh = blockIdx.y;
    int b = bh >> 4, h = bh & 15;
    int i0 = blockIdx.x * 128;
    int tid = threadIdx.x;
    int w = tid >> 5, lane = tid & 31;
    int g = lane >> 2, t = lane & 3;
    int wm = 16 * w;
    int bS = b * S;

    const float* mrow = &g_masses[(b * NHEADS + h) * S];
    for (int i = tid; i < S; i += 256) ms[i] = mrow[i];
    __syncthreads();

    float coefl = fabsf(G[h]) * L2E;

    float acc[8][4] = {};
    float sacc[4] = {};
    int niter = S >> 7;

    // prologue: tile 0 into buffer 0
    v_fill(Vbuf, x, bS, 0, h, tid);
    p_gen(Pbuf, ms, i0, 0, S, coefl, w, lane);
    __syncthreads();

    for (int it = 0; it < niter; it++) {
        int buf = it & 1;
        const uint32_t* Ph = Pbuf + buf * 128 * PSTR;
        const uint32_t* Vb = Vbuf + buf * 64 * VSTR;

        // ---- MMA on current buffers: 8 k16-chunks x (8 n-tiles + rowsum)
#pragma unroll
        for (int kc = 0; kc < 8; kc++) {
            uint32_t a[4];
            int ra = (wm + g) * PSTR + 8 * kc + t;
            int rb = ra + 8 * PSTR;
            a[0] = Ph[ra];     a[1] = Ph[rb];
            a[2] = Ph[ra + 4]; a[3] = Ph[rb + 4];
#pragma unroll
            for (int nt = 0; nt < 8; nt++) {
                uint32_t br[2];
                br[0] = Vb[(8 * kc + t) * VSTR + nt * 8 + g];
                br[1] = Vb[(8 * kc + t + 4) * VSTR + nt * 8 + g];
                mma_f16(acc[nt], a, br);
            }
            uint32_t ones[2] = {0x3C003C00u, 0x3C003C00u};
            mma_f16(sacc, a, ones);
        }

        // ---- fill/gen next tile into the other buffer (overlaps MMAs
        //      of slower warps; LDGs can hoist over this warp's MMA tail)
        if (it + 1 < niter) {
            int jt = (it + 1) << 7;
            uint32_t* Pn = Pbuf + (buf ^ 1) * 128 * PSTR;
            uint32_t* Vn = Vbuf + (buf ^ 1) * 64 * VSTR;
            v_fill(Vn, x, bS, jt, h, tid);
            p_gen(Pn, ms, i0, jt, S, coefl, w, lane);
        }
        __syncthreads();
    }

    float r0 = 1.0f / sacc[0];
    float r1 = 1.0f / sacc[2];
    size_t w0 = (((size_t)(bS + i0 + wm + g)) * DM + h * HD) >> 1;   // fp16x2 words
    size_t w1 = w0 + (size_t)4 * DM;                                  // +8 rows
#pragma unroll
    for (int nt = 0; nt < 8; nt++) {
        __half2 o0 = __floats2half2_rn(acc[nt][0] * r0, acc[nt][1] * r0);
        __half2 o1 = __floats2half2_rn(acc[nt][2] * r1, acc[nt][3] * r1);
        g_O[w0 + nt * 4 + t] = *(uint32_t*)&o0;
        g_O[w1 + nt * 4 + t] = *(uint32_t*)&o1;
    }
}

// ---------------------------------------------------------------------------
// Kernel 4: Y = O @ Wc^T, fp16 mma.sync m16n8k16, cp.async double-buffered.
// ---------------------------------------------------------------------------
__global__ __launch_bounds__(256, 2)
void out_gemm(float* __restrict__ Y) {
    extern __shared__ uint32_t sm_g[];
    uint32_t* As = sm_g;                 // [2][128][32] fp16x2 words
    uint32_t* Bs = sm_g + 2 * 128 * 32;

    int n0 = blockIdx.y * 128, j0 = blockIdx.x * 128;
    int tid = threadIdx.x;
    int w = tid >> 5, lane = tid & 31;
    int g = lane >> 2, t = lane & 3;
    int wm = (w >> 2) * 64, wn = (w & 3) * 32;
    int swz = g << 2;

    float acc[4][4][4] = {};

    int cr[4], cc[4];
#pragma unroll
    for (int v = 0; v < 4; v++) {
        int idx4 = v * 256 + tid;
        cr[v] = idx4 >> 3;
        cc[v] = (idx4 & 7) * 4;
    }

#define OG_ISSUE(buf, k0w)                                                       \
    do {                                                                         \
        _Pragma("unroll")                                                        \
        for (int v = 0; v < 4; v++) {                                            \
            int r = cr[v], c = cc[v];                                            \
            int so = r * 32 + (c ^ ((r & 7) << 2));                              \
            uint32_t dA = (uint32_t)__cvta_generic_to_shared(&As[(buf)*4096 + so]); \
            const uint32_t* sA = &g_O[(size_t)(n0 + r) * (DM / 2) + (k0w) + c];  \
            asm volatile("cp.async.cg.shared.global [%0], [%1], 16;" ::"r"(dA), "l"(sA)); \
            uint32_t dB = (uint32_t)__cvta_generic_to_shared(&Bs[(buf)*4096 + so]); \
            const uint32_t* sB = &g_Wc[(size_t)(j0 + r) * (DM / 2) + (k0w) + c]; \
            asm volatile("cp.async.cg.shared.global [%0], [%1], 16;" ::"r"(dB), "l"(sB)); \
        }                                                                        \
        asm volatile("cp.async.commit_group;");                                  \
    } while (0)

    OG_ISSUE(0, 0);

    for (int ki = 0; ki < DM / 64; ki++) {
        asm volatile("cp.async.wait_group 0;");
        __syncthreads();
        if (ki + 1 < DM / 64) OG_ISSUE((ki + 1) & 1, (ki + 1) * 32);

        const uint32_t* Ab = &As[(ki & 1) * 4096];
        const uint32_t* Bb = &Bs[(ki & 1) * 4096];
#pragma unroll
        for (int ks = 0; ks < 4; ks++) {
            int k = ks * 8;
            uint32_t a[4][4], bf[4][2];
#pragma unroll
            for (int mt = 0; mt < 4; mt++) {
                int r = wm + mt * 16 + g;
                a[mt][0] = Ab[r * 32 + ((k + t) ^ swz)];
                a[mt][1] = Ab[(r + 8) * 32 + ((k + t) ^ swz)];
                a[mt][2] = Ab[r * 32 + ((k + t + 4) ^ swz)];
                a[mt][3] = Ab[(r + 8) * 32 + ((k + t + 4) ^ swz)];
            }
#pragma unroll
            for (int nt = 0; nt < 4; nt++) {
                int r = wn + nt * 8 + g;
                bf[nt][0] = Bb[r * 32 + ((k + t) ^ swz)];
                bf[nt][1] = Bb[r * 32 + ((k + t + 4) ^ swz)];
            }
#pragma unroll
            for (int mt = 0; mt < 4; mt++)
#pragma unroll
                for (int nt = 0; nt < 4; nt++)
                    mma_f16(acc[mt][nt], a[mt], bf[nt]);
        }
    }
#pragma unroll
    for (int mt = 0; mt < 4; mt++) {
        int m = n0 + wm + mt * 16 + g;
#pragma unroll
        for (int nt = 0; nt < 4; nt++) {
            int j = j0 + wn + nt * 8 + 2 * t;
            float2 v0, v1;
            v0.x = acc[mt][nt][0]; v0.y = acc[mt][nt][1];
            v1.x = acc[mt][nt][2]; v1.y = acc[mt][nt][3];
            *(float2*)&Y[(size_t)m * DM + j] = v0;
            *(float2*)&Y[(size_t)(m + 8) * DM + j] = v1;
        }
    }
}

// ---------------------------------------------------------------------------
extern "C" void kernel_launch(void* const* d_in, const int* in_sizes, int n_in,
                              void* d_out, int out_size) {
    const float* x   = (const float*)d_in[0];   // [B,S,1024]
    const float* pos = (const float*)d_in[1];   // [S,64]
    const float* Wm  = (const float*)d_in[2];   // [16,64]
    const float* G   = (const float*)d_in[3];   // [16]
    const float* Wo  = (const float*)d_in[4];   // [1024,1024]
    float* out = (float*)d_out;                 // [B,S,1024]

    int S = in_sizes[1] / PDIM;
    int B = in_sizes[0] / (S * DM);

    int ATTN_SMEM = S * 4 + 2 * 128 * PSTR * 4 + 2 * 64 * VSTR * 4;
    static const int GEMM_SMEM = 4 * 128 * 32 * 4;
    cudaFuncSetAttribute(attn_kernel, cudaFuncAttributeMaxDynamicSharedMemorySize, ATTN_SMEM);
    cudaFuncSetAttribute(out_gemm, cudaFuncAttributeMaxDynamicSharedMemorySize, GEMM_SMEM);

    int nwarps = B * NHEADS * S;
    mass_kernel<<<nwarps / 8, 256>>>(x, Wm, S);

    wcvt_kernel<<<DM * DM / 2048, 256>>>(Wo);

    dim3 gd(S / 64, S / 64);
    dist_kernel<<<gd, 256>>>(pos, S);

    dim3 ga(S / 128, B * NHEADS);
    attn_kernel<<<ga, 256, ATTN_SMEM>>>(x, G, S);

    dim3 gg(DM / 128, (B * S) / 128);
    out_gemm<<<gg, 256, GEMM_SMEM>>>(out);
}

// round 12
// speedup vs baseline: 1.9609x; 1.0655x over previous
#include <cuda_runtime.h>
#include <cuda_fp16.h>
#include <math.h>
#include <stdint.h>

#define NHEADS 16
#define HD 64
#define DM 1024
#define PDIM 64
#define MAXS 2048
#define MAXB 2
#define L2E 1.4426950408889634f
#define PSTR 68     // P smem row stride (fp16x2 words); a-frag banks 4g+t distinct
#define VSTR 72     // V smem row stride (fp16x2 words); b-frag banks conflict-free

// scratch (device globals — no runtime allocation)
__device__ float g_masses[MAXB * NHEADS * MAXS];                 // [B,H,S]
__device__ float g_invd[(size_t)MAXS * MAXS];                    // 1 / dist_sq_mod
__device__ uint32_t g_O[(size_t)MAXB * MAXS * DM / 2];           // attn out, fp16x2
__device__ uint32_t g_Wc[(size_t)DM * DM / 2];                   // W_out, fp16x2

// ---------------- helpers ----------------
__device__ __forceinline__ float ex2(float v) {
    float y;
    asm("ex2.approx.ftz.f32 %0, %1;" : "=f"(y) : "f"(v));
    return y;
}
// fp16 m16n8k16, fp32 accum
__device__ __forceinline__ void mma_f16(float* d, const uint32_t* a, const uint32_t* b) {
    asm volatile(
        "mma.sync.aligned.m16n8k16.row.col.f32.f16.f16.f32 "
        "{%0,%1,%2,%3}, {%4,%5,%6,%7}, {%8,%9}, {%0,%1,%2,%3};"
        : "+f"(d[0]), "+f"(d[1]), "+f"(d[2]), "+f"(d[3])
        : "r"(a[0]), "r"(a[1]), "r"(a[2]), "r"(a[3]), "r"(b[0]), "r"(b[1]));
}

// ---------------------------------------------------------------------------
// Kernel 1: masses[b,h,s] = softplus( dot(xh[b,s,h,:], W_mass[h,:]) )
// ---------------------------------------------------------------------------
__global__ void mass_kernel(const float* __restrict__ x,
                            const float* __restrict__ Wm, int S) {
    int gw   = (blockIdx.x * 256 + threadIdx.x) >> 5;
    int lane = threadIdx.x & 31;
    int s = gw % S;
    int h = (gw / S) & (NHEADS - 1);
    int b = gw / (S * NHEADS);
    const float* xr = x + ((size_t)(b * S + s)) * DM + h * HD;
    float t = xr[lane] * Wm[h * HD + lane] + xr[lane + 32] * Wm[h * HD + lane + 32];
#pragma unroll
    for (int o = 16; o; o >>= 1) t += __shfl_xor_sync(0xffffffffu, t, o);
    if (lane == 0) {
        float m = (t > 20.f) ? t : log1pf(expf(t));
        g_masses[(b * NHEADS + h) * S + s] = m;
    }
}

// ---------------------------------------------------------------------------
// Kernel 1b: pre-convert W_out to fp16x2
// ---------------------------------------------------------------------------
__global__ void wcvt_kernel(const float* __restrict__ W) {
    int i = blockIdx.x * 256 + threadIdx.x;     // 8 floats / thread
    float4 v0 = *(const float4*)&W[(size_t)i * 8];
    float4 v1 = *(const float4*)&W[(size_t)i * 8 + 4];
    __half2 h0 = __floats2half2_rn(v0.x, v0.y);
    __half2 h1 = __floats2half2_rn(v0.z, v0.w);
    __half2 h2 = __floats2half2_rn(v1.x, v1.y);
    __half2 h3 = __floats2half2_rn(v1.z, v1.w);
    uint4 o;
    o.x = *(uint32_t*)&h0; o.y = *(uint32_t*)&h1;
    o.z = *(uint32_t*)&h2; o.w = *(uint32_t*)&h3;
    *(uint4*)&g_Wc[(size_t)i * 4] = o;
}

// ---------------------------------------------------------------------------
// Kernel 2: g_invd[i,j] = 1 / max( d2*(1+0.15*cos(sqrt(d2+1e-6))), 1e-6 )
// ---------------------------------------------------------------------------
__global__ void dist_kernel(const float* __restrict__ pos, int S) {
    __shared__ float Pi[PDIM][65];
    __shared__ float Pj[PDIM][65];
    int i0 = blockIdx.x * 64, j0 = blockIdx.y * 64;
    int tid = threadIdx.x;
#pragma unroll
    for (int v = 0; v < 16; v++) {
        int e = v * 256 + tid;
        int r = e >> 6, p = e & 63;
        Pi[p][r] = pos[(size_t)(i0 + r) * PDIM + p];
        Pj[p][r] = pos[(size_t)(j0 + r) * PDIM + p];
    }
    __syncthreads();
    int ty = tid >> 4, tx = tid & 15;
    float acc[4][4] = {};
#pragma unroll
    for (int p = 0; p < PDIM; p++) {
        float a[4], bb[4];
#pragma unroll
        for (int i = 0; i < 4; i++) a[i] = Pi[p][ty * 4 + i];
#pragma unroll
        for (int j = 0; j < 4; j++) bb[j] = Pj[p][tx * 4 + j];
#pragma unroll
        for (int i = 0; i < 4; i++)
#pragma unroll
            for (int j = 0; j < 4; j++) {
                float d = a[i] - bb[j];
                acc[i][j] = fmaf(d, d, acc[i][j]);
            }
    }
#pragma unroll
    for (int i = 0; i < 4; i++)
#pragma unroll
        for (int j = 0; j < 4; j++) {
            int ii = i0 + ty * 4 + i, jj = j0 + tx * 4 + j;
            float v = acc[i][j];
            float dn = sqrtf(v + 1e-6f);
            float d2 = v * (1.f + 0.15f * cosf(dn));
            d2 = fmaxf(d2, 1e-6f);
            g_invd[(size_t)ii * S + jj] = 1.0f / d2;
        }
}

// ---------------------------------------------------------------------------
// Kernel 3: attention in fp16 (P' = exp(f-50), range (0,1]). 256-row i-tile,
// warp = 32 rows x 64 cols (two m16 blocks sharing B fragments -> half the
// V-tile re-reads). Phases: [fill V + gen P] / sync / [MMA] / sync.
// Rowsum via ones-MMA on rounded fp16 P. Output g_O written fp16x2.
// ---------------------------------------------------------------------------
__global__ __launch_bounds__(256, 2)
void attn_kernel(const float* __restrict__ x,
                 const float* __restrict__ G, int S) {
    extern __shared__ char sm[];
    float* ms = (float*)sm;                          // [S]
    uint32_t* Ph = (uint32_t*)(sm + (size_t)S * 4);  // [256][PSTR] fp16x2 (j pairs)
    uint32_t* Vb = Ph + 256 * PSTR;                  // [64][VSTR]  fp16x2 (k pairs)

    int bh = blockIdx.y;
    int b = bh >> 4, h = bh & 15;
    int i0 = blockIdx.x * 256;
    int tid = threadIdx.x;
    int w = tid >> 5, lane = tid & 31;
    int g = lane >> 2, t = lane & 3;
    int wm = 32 * w;
    int bS = b * S;

    const float* mrow = &g_masses[(b * NHEADS + h) * S];
    for (int i = tid; i < S; i += 256) ms[i] = mrow[i];
    __syncthreads();

    float coefl = fabsf(G[h]) * L2E;
    const float C50L = 50.0f * L2E;

    float acc[2][8][4] = {};
    float sacc[2][4] = {};
    int niter = S >> 7;

    for (int it = 0; it < niter; it++) {
        int jt = it << 7;

        // ---- V fill: Vb[k2][n] = {V[2k2][n], V[2k2+1][n]} fp16x2
#pragma unroll
        for (int v4 = 0; v4 < 4; v4++) {
            int slot = v4 * 256 + tid;
            int n4 = slot & 15, k2 = slot >> 4;
            const float* xp = &x[((size_t)(bS + jt + 2 * k2)) * DM + h * HD + n4 * 4];
            float4 r0 = *(const float4*)xp;
            float4 r1 = *(const float4*)(xp + DM);
            __half2 h0 = __floats2half2_rn(r0.x, r1.x);
            __half2 h1 = __floats2half2_rn(r0.y, r1.y);
            __half2 h2 = __floats2half2_rn(r0.z, r1.z);
            __half2 h3 = __floats2half2_rn(r0.w, r1.w);
            uint4 o;
            o.x = *(uint32_t*)&h0; o.y = *(uint32_t*)&h1;
            o.z = *(uint32_t*)&h2; o.w = *(uint32_t*)&h3;
            *(uint4*)&Vb[k2 * VSTR + n4 * 4] = o;
        }
        // ---- P gen: 256 rows; row per (v,w); 4 cols/thread
#pragma unroll
        for (int v = 0; v < 32; v++) {
            int r = v * 8 + w;
            float cm = coefl * ms[i0 + r];
            float4 dv = *(const float4*)&g_invd[(size_t)(i0 + r) * S + jt + 4 * lane];
            float4 mv = *(const float4*)&ms[jt + 4 * lane];
            float e0 = ex2(fminf(cm * mv.x * dv.x, C50L) - C50L);
            float e1 = ex2(fminf(cm * mv.y * dv.y, C50L) - C50L);
            float e2 = ex2(fminf(cm * mv.z * dv.z, C50L) - C50L);
            float e3 = ex2(fminf(cm * mv.w * dv.w, C50L) - C50L);
            __half2 p0 = __floats2half2_rn(e0, e1);
            __half2 p1 = __floats2half2_rn(e2, e3);
            uint2 o;
            o.x = *(uint32_t*)&p0; o.y = *(uint32_t*)&p1;
            *(uint2*)&Ph[r * PSTR + 2 * lane] = o;
        }
        __syncthreads();   // tiles ready

        // ---- MMA: 8 k16-chunks x (8 n-tiles x 2 m-blocks + 2 rowsums)
#pragma unroll
        for (int kc = 0; kc < 8; kc++) {
            uint32_t a0[4], a1[4];
            int ra = (wm + g) * PSTR + 8 * kc + t;
            a0[0] = Ph[ra];              a0[1] = Ph[ra + 8 * PSTR];
            a0[2] = Ph[ra + 4];          a0[3] = Ph[ra + 8 * PSTR + 4];
            int rb = ra + 16 * PSTR;
            a1[0] = Ph[rb];              a1[1] = Ph[rb + 8 * PSTR];
            a1[2] = Ph[rb + 4];          a1[3] = Ph[rb + 8 * PSTR + 4];
#pragma unroll
            for (int nt = 0; nt < 8; nt++) {
                uint32_t br[2];
                br[0] = Vb[(8 * kc + t) * VSTR + nt * 8 + g];
                br[1] = Vb[(8 * kc + t + 4) * VSTR + nt * 8 + g];
                mma_f16(acc[0][nt], a0, br);
                mma_f16(acc[1][nt], a1, br);
            }
            uint32_t ones[2] = {0x3C003C00u, 0x3C003C00u};
            mma_f16(sacc[0], a0, ones);
            mma_f16(sacc[1], a1, ones);
        }
        __syncthreads();   // MMA reads done before next fill
    }

    // epilogue: two m16 blocks per warp
#pragma unroll
    for (int mb = 0; mb < 2; mb++) {
        float r0 = 1.0f / sacc[mb][0];
        float r1 = 1.0f / sacc[mb][2];
        size_t w0 = (((size_t)(bS + i0 + wm + 16 * mb + g)) * DM + h * HD) >> 1;
        size_t w1 = w0 + (size_t)4 * DM;   // +8 rows (fp16x2 words)
#pragma unroll
        for (int nt = 0; nt < 8; nt++) {
            __half2 o0 = __floats2half2_rn(acc[mb][nt][0] * r0, acc[mb][nt][1] * r0);
            __half2 o1 = __floats2half2_rn(acc[mb][nt][2] * r1, acc[mb][nt][3] * r1);
            g_O[w0 + nt * 4 + t] = *(uint32_t*)&o0;
            g_O[w1 + nt * 4 + t] = *(uint32_t*)&o1;
        }
    }
}

// ---------------------------------------------------------------------------
// Kernel 4: Y = O @ Wc^T, fp16 mma.sync m16n8k16, cp.async double-buffered.
// ---------------------------------------------------------------------------
__global__ __launch_bounds__(256, 2)
void out_gemm(float* __restrict__ Y) {
    extern __shared__ uint32_t sm_g[];
    uint32_t* As = sm_g;                 // [2][128][32] fp16x2 words
    uint32_t* Bs = sm_g + 2 * 128 * 32;

    int n0 = blockIdx.y * 128, j0 = blockIdx.x * 128;
    int tid = threadIdx.x;
    int w = tid >> 5, lane = tid & 31;
    int g = lane >> 2, t = lane & 3;
    int wm = (w >> 2) * 64, wn = (w & 3) * 32;
    int swz = g << 2;

    float acc[4][4][4] = {};

    int cr[4], cc[4];
#pragma unroll
    for (int v = 0; v < 4; v++) {
        int idx4 = v * 256 + tid;
        cr[v] = idx4 >> 3;
        cc[v] = (idx4 & 7) * 4;
    }

#define OG_ISSUE(buf, k0w)                                                       \
    do {                                                                         \
        _Pragma("unroll")                                                        \
        for (int v = 0; v < 4; v++) {                                            \
            int r = cr[v], c = cc[v];                                            \
            int so = r * 32 + (c ^ ((r & 7) << 2));                              \
            uint32_t dA = (uint32_t)__cvta_generic_to_shared(&As[(buf)*4096 + so]); \
            const uint32_t* sA = &g_O[(size_t)(n0 + r) * (DM / 2) + (k0w) + c];  \
            asm volatile("cp.async.cg.shared.global [%0], [%1], 16;" ::"r"(dA), "l"(sA)); \
            uint32_t dB = (uint32_t)__cvta_generic_to_shared(&Bs[(buf)*4096 + so]); \
            const uint32_t* sB = &g_Wc[(size_t)(j0 + r) * (DM / 2) + (k0w) + c]; \
            asm volatile("cp.async.cg.shared.global [%0], [%1], 16;" ::"r"(dB), "l"(sB)); \
        }                                                                        \
        asm volatile("cp.async.commit_group;");                                  \
    } while (0)

    OG_ISSUE(0, 0);

    for (int ki = 0; ki < DM / 64; ki++) {
        asm volatile("cp.async.wait_group 0;");
        __syncthreads();
        if (ki + 1 < DM / 64) OG_ISSUE((ki + 1) & 1, (ki + 1) * 32);

        const uint32_t* Ab = &As[(ki & 1) * 4096];
        const uint32_t* Bb = &Bs[(ki & 1) * 4096];
#pragma unroll
        for (int ks = 0; ks < 4; ks++) {
            int k = ks * 8;
            uint32_t a[4][4], bf[4][2];
#pragma unroll
            for (int mt = 0; mt < 4; mt++) {
                int r = wm + mt * 16 + g;
                a[mt][0] = Ab[r * 32 + ((k + t) ^ swz)];
                a[mt][1] = Ab[(r + 8) * 32 + ((k + t) ^ swz)];
                a[mt][2] = Ab[r * 32 + ((k + t + 4) ^ swz)];
                a[mt][3] = Ab[(r + 8) * 32 + ((k + t + 4) ^ swz)];
            }
#pragma unroll
            for (int nt = 0; nt < 4; nt++) {
                int r = wn + nt * 8 + g;
                bf[nt][0] = Bb[r * 32 + ((k + t) ^ swz)];
                bf[nt][1] = Bb[r * 32 + ((k + t + 4) ^ swz)];
            }
#pragma unroll
            for (int mt = 0; mt < 4; mt++)
#pragma unroll
                for (int nt = 0; nt < 4; nt++)
                    mma_f16(acc[mt][nt], a[mt], bf[nt]);
        }
    }
#pragma unroll
    for (int mt = 0; mt < 4; mt++) {
        int m = n0 + wm + mt * 16 + g;
#pragma unroll
        for (int nt = 0; nt < 4; nt++) {
            int j = j0 + wn + nt * 8 + 2 * t;
            float2 v0, v1;
            v0.x = acc[mt][nt][0]; v0.y = acc[mt][nt][1];
            v1.x = acc[mt][nt][2]; v1.y = acc[mt][nt][3];
            *(float2*)&Y[(size_t)m * DM + j] = v0;
            *(float2*)&Y[(size_t)(m + 8) * DM + j] = v1;
        }
    }
}

// ---------------------------------------------------------------------------
extern "C" void kernel_launch(void* const* d_in, const int* in_sizes, int n_in,
                              void* d_out, int out_size) {
    const float* x   = (const float*)d_in[0];   // [B,S,1024]
    const float* pos = (const float*)d_in[1];   // [S,64]
    const float* Wm  = (const float*)d_in[2];   // [16,64]
    const float* G   = (const float*)d_in[3];   // [16]
    const float* Wo  = (const float*)d_in[4];   // [1024,1024]
    float* out = (float*)d_out;                 // [B,S,1024]

    int S = in_sizes[1] / PDIM;
    int B = in_sizes[0] / (S * DM);

    int ATTN_SMEM = S * 4 + 256 * PSTR * 4 + 64 * VSTR * 4;
    static const int GEMM_SMEM = 4 * 128 * 32 * 4;
    cudaFuncSetAttribute(attn_kernel, cudaFuncAttributeMaxDynamicSharedMemorySize, ATTN_SMEM);
    cudaFuncSetAttribute(out_gemm, cudaFuncAttributeMaxDynamicSharedMemorySize, GEMM_SMEM);

    int nwarps = B * NHEADS * S;
    mass_kernel<<<nwarps / 8, 256>>>(x, Wm, S);

    wcvt_kernel<<<DM * DM / 2048, 256>>>(Wo);

    dim3 gd(S / 64, S / 64);
    dist_kernel<<<gd, 256>>>(pos, S);

    dim3 ga(S / 256, B * NHEADS);
    attn_kernel<<<ga, 256, ATTN_SMEM>>>(x, G, S);

    dim3 gg(DM / 128, (B * S) / 128);
    out_gemm<<<gg, 256, GEMM_SMEM>>>(out);
}